// round 7
// baseline (speedup 1.0000x reference)
#include <cuda_runtime.h>
#include <cuda_fp16.h>
#include <cstdint>
#include <math.h>

#define Bsz 2048
#define Tsz 60
#define Fsz 89
#define Hsz 1024
#define OUTsz 30

#define NSTG 35            // 32 k-stages of h@U + 3 of x@W (F padded to 96)
#define ROWB 80            // smem row pitch: 32 fp16 (64B) + 16B pad
#define MAT_A 10240        // 128 rows * 80
#define STAGE_B 30720      // A (10240) + B (256*80=20480)
#define NPIPE 4
#define SMEM_TOTAL (NPIPE * STAGE_B)   // 122880

// ---------------- device globals (no runtime allocation) ----------------
__device__ __align__(16) __half g_UB[(size_t)4096 * 1024];     // [np][k], np = 4*j+gate
__device__ __align__(16) __half g_WB[(size_t)4096 * 96];       // [np][k]
__device__ __align__(16) __half g_xB[(size_t)2048 * 60 * 96];  // [m][t][96]
__device__ __align__(16) __half g_hB[2][(size_t)2048 * 1024];  // ping-pong [m][k]
__device__ float g_c[(size_t)2048 * 1024];
__device__ float g_hflat[(size_t)2048 * 1024];
__device__ float g_bil[4096];

// ---------------- PTX helpers (baseline ISA only) ----------------
__device__ __forceinline__ uint32_t smem_u32(const void* p) {
    uint32_t a;
    asm("{ .reg .u64 t; cvta.to.shared.u64 t, %1; cvt.u32.u64 %0, t; }" : "=r"(a) : "l"(p));
    return a;
}
#define CP16(dst, src) \
    asm volatile("cp.async.cg.shared.global [%0], [%1], 16;" :: "r"(dst), "l"(src))
#define CPCOMMIT() asm volatile("cp.async.commit_group;" ::: "memory")
#define CPWAIT2()  asm volatile("cp.async.wait_group 2;" ::: "memory")
#define CPWAIT0()  asm volatile("cp.async.wait_group 0;" ::: "memory")

__device__ __forceinline__ void ldm4(uint32_t* r, uint32_t addr) {
    asm volatile("ldmatrix.sync.aligned.m8n8.x4.shared.b16 {%0,%1,%2,%3}, [%4];"
        : "=r"(r[0]), "=r"(r[1]), "=r"(r[2]), "=r"(r[3]) : "r"(addr));
}
__device__ __forceinline__ void mma16816(float* d, const uint32_t* a, const uint32_t* b) {
    asm volatile(
        "mma.sync.aligned.m16n8k16.row.col.f32.f16.f16.f32 "
        "{%0,%1,%2,%3}, {%4,%5,%6,%7}, {%8,%9}, {%0,%1,%2,%3};"
        : "+f"(d[0]), "+f"(d[1]), "+f"(d[2]), "+f"(d[3])
        : "r"(a[0]), "r"(a[1]), "r"(a[2]), "r"(a[3]), "r"(b[0]), "r"(b[1]));
}

// ---------------- repack / init kernels ----------------
__global__ void k_zero() {
    size_t i = (size_t)blockIdx.x * 256 + threadIdx.x;
    if (i < (size_t)Bsz * Hsz) {
        g_c[i] = 0.0f;
        g_hB[0][i] = __float2half(0.0f);
    }
}
__global__ void k_repack_U(const float* __restrict__ U) {
    size_t i = (size_t)blockIdx.x * 256 + threadIdx.x;
    if (i >= (size_t)1024 * 4096) return;
    int k = (int)(i >> 12), c = (int)(i & 4095);
    int np = 4 * (c & 1023) + (c >> 10);
    g_UB[(size_t)np * 1024 + k] = __float2half(U[i]);
}
__global__ void k_repack_W(const float* __restrict__ W) {
    size_t i = (size_t)blockIdx.x * 256 + threadIdx.x;
    if (i >= (size_t)96 * 4096) return;
    int k = (int)(i / 4096), c = (int)(i % 4096);
    float v = (k < Fsz) ? W[(size_t)k * 4096 + c] : 0.0f;
    int np = 4 * (c & 1023) + (c >> 10);
    g_WB[(size_t)np * 96 + k] = __float2half(v);
}
__global__ void k_repack_x(const float* __restrict__ x) {
    size_t i = (size_t)blockIdx.x * 256 + threadIdx.x;
    if (i >= (size_t)Bsz * Tsz * 96) return;
    int k = (int)(i % 96);
    size_t mt_ = i / 96;
    float v = (k < Fsz) ? x[mt_ * Fsz + k] : 0.0f;
    g_xB[i] = __float2half(v);
}
__global__ void k_repack_b(const float* __restrict__ b) {
    int c = blockIdx.x * 256 + threadIdx.x;
    if (c < 4096) g_bil[4 * (c & 1023) + (c >> 10)] = b[c];
}

// ---------------- LSTM gate update ----------------
__device__ __forceinline__ void gate_update(int m, int j, float zi, float zf,
                                            float zg, float zo, int t, int dst) {
    size_t idx = (size_t)m * Hsz + j;
    float ig = 1.0f / (1.0f + expf(-zi));
    float fg = 1.0f / (1.0f + expf(-zf));
    float og = 1.0f / (1.0f + expf(-zo));
    float c = fg * g_c[idx] + ig * fmaxf(zg, 0.0f);
    g_c[idx] = c;
    float h = og * fmaxf(c, 0.0f);
    if (t == Tsz - 1) g_hflat[idx] = h;
    else              g_hB[dst][idx] = __float2half(h);
}

// ---------------- per-timestep fused GEMM + gate kernel ----------------
// CTA tile 128(M) x 256(N), 8 warps (2x4), warp tile 64x64, fp16, 4-stage pipe.
__global__ __launch_bounds__(256) void step_kernel(int t) {
    extern __shared__ __align__(128) char smem[];
    const int tid  = threadIdx.x;
    const int nt   = blockIdx.x;      // 0..15
    const int mt   = blockIdx.y;      // 0..15
    const int wid  = tid >> 5, lane = tid & 31;
    const int wm   = wid >> 2, wn = wid & 3;
    const int src  = t & 1, dst = src ^ 1;

    float acc[4][8][4];
#pragma unroll
    for (int a = 0; a < 4; a++)
#pragma unroll
        for (int b = 0; b < 8; b++)
#pragma unroll
            for (int c = 0; c < 4; c++) acc[a][b][c] = 0.0f;

    const int lr  = lane & 15;
    const int lkb = ((lane >> 4) & 1) * 16;

    auto issue_stage = [&](int s) {
        if (s < NSTG) {
            const __half *aP, *bP;
            int aStr, bStr; size_t aOff, bOff;
            if (s < 32) {
                aP = g_hB[src]; aStr = 1024; aOff = (size_t)32 * s;
                bP = g_UB;      bStr = 1024; bOff = (size_t)32 * s;
            } else {
                int i = s - 32;
                aP = g_xB; aStr = Tsz * 96; aOff = (size_t)t * 96 + 32 * i;
                bP = g_WB; bStr = 96;       bOff = (size_t)32 * i;
            }
            char* base = smem + (s & (NPIPE - 1)) * STAGE_B;
#pragma unroll
            for (int it = 0; it < 6; it++) {
                int q = it * 256 + tid;            // 1536 chunks of 16B
                const __half* gp;
                uint32_t d;
                if (q < 512) {
                    int row = q >> 2, kc = q & 3;
                    gp = aP + (size_t)(mt * 128 + row) * aStr + aOff + kc * 8;
                    d = smem_u32(base + row * ROWB + kc * 16);
                } else {
                    int p = q - 512;
                    int row = p >> 2, kc = p & 3;
                    gp = bP + (size_t)(nt * 256 + row) * bStr + bOff + kc * 8;
                    d = smem_u32(base + MAT_A + row * ROWB + kc * 16);
                }
                CP16(d, gp);
            }
        }
        CPCOMMIT();   // empty group past the end keeps wait_group bookkeeping simple
    };

    auto compute_stage = [&](int buf) {
        uint32_t aBase = smem_u32(smem + buf * STAGE_B) + lr * ROWB + lkb;
        uint32_t bBase = aBase + MAT_A;
#pragma unroll
        for (int kk = 0; kk < 2; kk++) {
            uint32_t aF[4][4], bF[8][2];
#pragma unroll
            for (int im = 0; im < 4; im++)
                ldm4(aF[im], aBase + (wm * 64 + im * 16) * ROWB + kk * 32);
#pragma unroll
            for (int ig = 0; ig < 4; ig++) {
                uint32_t r[4];
                ldm4(r, bBase + (wn * 64 + ig * 16) * ROWB + kk * 32);
                bF[ig * 2][0] = r[0];     bF[ig * 2][1] = r[2];
                bF[ig * 2 + 1][0] = r[1]; bF[ig * 2 + 1][1] = r[3];
            }
#pragma unroll
            for (int im = 0; im < 4; im++)
#pragma unroll
                for (int iu = 0; iu < 8; iu++)
                    mma16816(acc[im][iu], aF[im], bF[iu]);
        }
    };

    issue_stage(0);
    issue_stage(1);
    issue_stage(2);
#pragma unroll 1
    for (int s = 0; s < NSTG; s++) {
        CPWAIT2();
        __syncthreads();
        issue_stage(s + 3);
        compute_stage(s & (NPIPE - 1));
    }

    // ---------------- fused gate epilogue ----------------
    const int g  = lane >> 2;
    const int t4 = lane & 3;
#pragma unroll
    for (int im = 0; im < 4; im++) {
#pragma unroll
        for (int iu = 0; iu < 8; iu++) {
            int np = nt * 256 + wn * 64 + iu * 8 + 2 * t4;
            float b0 = g_bil[np], b1 = g_bil[np + 1];
            float z0 = acc[im][iu][0] + b0;
            float z1 = acc[im][iu][1] + b1;
            float z2 = acc[im][iu][2] + b0;
            float z3 = acc[im][iu][3] + b1;
            float o0 = __shfl_xor_sync(0xFFFFFFFF, z0, 1);
            float o1 = __shfl_xor_sync(0xFFFFFFFF, z1, 1);
            float o2 = __shfl_xor_sync(0xFFFFFFFF, z2, 1);
            float o3 = __shfl_xor_sync(0xFFFFFFFF, z3, 1);
            if ((t4 & 1) == 0) {
                int j  = np >> 2;
                int m0 = mt * 128 + wm * 64 + im * 16 + g;
                gate_update(m0,     j, z0, z1, o0, o1, t, dst);
                gate_update(m0 + 8, j, z2, z3, o2, o3, t, dst);
            }
        }
    }
}

// ---------------- dense head ----------------
__global__ void dense_kernel(const float* __restrict__ Wd,
                             const float* __restrict__ bd,
                             float* __restrict__ out) {
    int m = blockIdx.x, o = threadIdx.x;
    if (o >= OUTsz) return;
    const float* hr = g_hflat + (size_t)m * Hsz;
    float acc = bd[o];
#pragma unroll 4
    for (int k = 0; k < Hsz; k++)
        acc = fmaf(hr[k], Wd[(size_t)k * OUTsz + o], acc);
    out[(size_t)m * OUTsz + o] = acc;
}

// ---------------------------------------------------------------------------
extern "C" void kernel_launch(void* const* d_in, const int* in_sizes, int n_in,
                              void* d_out, int out_size) {
    const float* x  = (const float*)d_in[0];
    const float* W  = (const float*)d_in[1];
    const float* U  = (const float*)d_in[2];
    const float* b  = (const float*)d_in[3];
    const float* Wd = (const float*)d_in[4];
    const float* bd = (const float*)d_in[5];
    float* out = (float*)d_out;

    static int attr_set = 0;
    if (!attr_set) {
        cudaFuncSetAttribute(step_kernel, cudaFuncAttributeMaxDynamicSharedMemorySize,
                             SMEM_TOTAL);
        attr_set = 1;
    }

    k_zero<<<(Bsz * Hsz + 255) / 256, 256>>>();
    k_repack_U<<<(1024 * 4096 + 255) / 256, 256>>>(U);
    k_repack_W<<<(96 * 4096 + 255) / 256, 256>>>(W);
    k_repack_x<<<(Bsz * Tsz * 96 + 255) / 256, 256>>>(x);
    k_repack_b<<<16, 256>>>(b);

    dim3 grid(16, 16);
    for (int t = 0; t < Tsz; t++)
        step_kernel<<<grid, 256, SMEM_TOTAL>>>(t);

    dense_kernel<<<Bsz, 32>>>(Wd, bd, out);
}

// round 8
// speedup vs baseline: 1.2564x; 1.2564x over previous
#include <cuda_runtime.h>
#include <cuda_fp16.h>
#include <cstdint>
#include <math.h>

#define Bsz 2048
#define Tsz 60
#define Fsz 89
#define Hsz 1024
#define OUTsz 30

#define NSTG 35            // 32 k-stages of h@U + 3 of x@W (F padded to 96)
#define ROWB 80            // smem row pitch: 32 fp16 (64B) + 16B pad
#define MAT_A 10240        // 128 rows * 80
#define STAGE_B 20480      // A (10240) + B (10240)
#define NPIPE 4
#define SMEM_TOTAL (NPIPE * STAGE_B)   // 81920 -> 2 CTAs/SM

// ---------------- device globals (no runtime allocation) ----------------
__device__ __align__(16) __half g_UB[(size_t)4096 * 1024];     // [np][k], np = 4*j+gate
__device__ __align__(16) __half g_WB[(size_t)4096 * 96];       // [np][k]
__device__ __align__(16) __half g_xB[(size_t)2048 * 60 * 96];  // [m][t][96]
__device__ __align__(16) __half g_hB[2][(size_t)2048 * 1024];  // ping-pong [m][k]
__device__ float g_c[(size_t)2048 * 1024];
__device__ float g_hflat[(size_t)2048 * 1024];
__device__ float g_bil[4096];

// ---------------- PTX helpers (baseline ISA only) ----------------
__device__ __forceinline__ uint32_t smem_u32(const void* p) {
    uint32_t a;
    asm("{ .reg .u64 t; cvta.to.shared.u64 t, %1; cvt.u32.u64 %0, t; }" : "=r"(a) : "l"(p));
    return a;
}
#define CP16(dst, src) \
    asm volatile("cp.async.cg.shared.global [%0], [%1], 16;" :: "r"(dst), "l"(src))
#define CPCOMMIT() asm volatile("cp.async.commit_group;" ::: "memory")
#define CPWAIT2()  asm volatile("cp.async.wait_group 2;" ::: "memory")

__device__ __forceinline__ void ldm4(uint32_t* r, uint32_t addr) {
    asm volatile("ldmatrix.sync.aligned.m8n8.x4.shared.b16 {%0,%1,%2,%3}, [%4];"
        : "=r"(r[0]), "=r"(r[1]), "=r"(r[2]), "=r"(r[3]) : "r"(addr));
}
__device__ __forceinline__ void mma16816(float* d, const uint32_t* a, const uint32_t* b) {
    asm volatile(
        "mma.sync.aligned.m16n8k16.row.col.f32.f16.f16.f32 "
        "{%0,%1,%2,%3}, {%4,%5,%6,%7}, {%8,%9}, {%0,%1,%2,%3};"
        : "+f"(d[0]), "+f"(d[1]), "+f"(d[2]), "+f"(d[3])
        : "r"(a[0]), "r"(a[1]), "r"(a[2]), "r"(a[3]), "r"(b[0]), "r"(b[1]));
}

// ---------------- repack / init kernels ----------------
__global__ void k_zero() {
    size_t i = (size_t)blockIdx.x * 256 + threadIdx.x;
    if (i < (size_t)Bsz * Hsz) {
        g_c[i] = 0.0f;
        g_hB[0][i] = __float2half(0.0f);
    }
}
__global__ void k_repack_U(const float* __restrict__ U) {
    size_t i = (size_t)blockIdx.x * 256 + threadIdx.x;
    if (i >= (size_t)1024 * 4096) return;
    int k = (int)(i >> 12), c = (int)(i & 4095);
    int np = 4 * (c & 1023) + (c >> 10);
    g_UB[(size_t)np * 1024 + k] = __float2half(U[i]);
}
__global__ void k_repack_W(const float* __restrict__ W) {
    size_t i = (size_t)blockIdx.x * 256 + threadIdx.x;
    if (i >= (size_t)96 * 4096) return;
    int k = (int)(i / 4096), c = (int)(i % 4096);
    float v = (k < Fsz) ? W[(size_t)k * 4096 + c] : 0.0f;
    int np = 4 * (c & 1023) + (c >> 10);
    g_WB[(size_t)np * 96 + k] = __float2half(v);
}
__global__ void k_repack_x(const float* __restrict__ x) {
    size_t i = (size_t)blockIdx.x * 256 + threadIdx.x;
    if (i >= (size_t)Bsz * Tsz * 96) return;
    int k = (int)(i % 96);
    size_t mt_ = i / 96;
    float v = (k < Fsz) ? x[mt_ * Fsz + k] : 0.0f;
    g_xB[i] = __float2half(v);
}
__global__ void k_repack_b(const float* __restrict__ b) {
    int c = blockIdx.x * 256 + threadIdx.x;
    if (c < 4096) g_bil[4 * (c & 1023) + (c >> 10)] = b[c];
}

// ---------------- LSTM gate update ----------------
__device__ __forceinline__ void gate_update(int m, int j, float zi, float zf,
                                            float zg, float zo, int t, int dst) {
    size_t idx = (size_t)m * Hsz + j;
    float ig = 1.0f / (1.0f + expf(-zi));
    float fg = 1.0f / (1.0f + expf(-zf));
    float og = 1.0f / (1.0f + expf(-zo));
    float c = fg * g_c[idx] + ig * fmaxf(zg, 0.0f);
    g_c[idx] = c;
    float h = og * fmaxf(c, 0.0f);
    if (t == Tsz - 1) g_hflat[idx] = h;
    else              g_hB[dst][idx] = __float2half(h);
}

// ---------------- per-timestep fused GEMM + gate kernel ----------------
// CTA tile 128(M) x 128(N), 8 warps (2x4), warp tile 64x32, fp16, 4-stage pipe,
// 2 CTAs/SM for latency hiding.
__global__ __launch_bounds__(256, 2) void step_kernel(int t) {
    extern __shared__ __align__(128) char smem[];
    const int tid  = threadIdx.x;
    const int nt   = blockIdx.x;      // 0..31 (128 np-cols)
    const int mt   = blockIdx.y;      // 0..15 (128 rows)
    const int wid  = tid >> 5, lane = tid & 31;
    const int wm   = wid >> 2, wn = wid & 3;
    const int src  = t & 1, dst = src ^ 1;

    float acc[4][4][4];
#pragma unroll
    for (int a = 0; a < 4; a++)
#pragma unroll
        for (int b = 0; b < 4; b++)
#pragma unroll
            for (int c = 0; c < 4; c++) acc[a][b][c] = 0.0f;

    const int lr  = lane & 15;
    const int lkb = ((lane >> 4) & 1) * 16;

    auto issue_stage = [&](int s) {
        if (s < NSTG) {
            const __half *aP, *bP;
            int aStr, bStr; size_t aOff, bOff;
            if (s < 32) {
                aP = g_hB[src]; aStr = 1024; aOff = (size_t)32 * s;
                bP = g_UB;      bStr = 1024; bOff = (size_t)32 * s;
            } else {
                int i = s - 32;
                aP = g_xB; aStr = Tsz * 96; aOff = (size_t)t * 96 + 32 * i;
                bP = g_WB; bStr = 96;       bOff = (size_t)32 * i;
            }
            char* base = smem + (s & (NPIPE - 1)) * STAGE_B;
#pragma unroll
            for (int it = 0; it < 4; it++) {
                int q = it * 256 + tid;            // 1024 chunks of 16B
                const __half* gp;
                uint32_t d;
                if (q < 512) {
                    int row = q >> 2, kc = q & 3;
                    gp = aP + (size_t)(mt * 128 + row) * aStr + aOff + kc * 8;
                    d = smem_u32(base + row * ROWB + kc * 16);
                } else {
                    int p = q - 512;
                    int row = p >> 2, kc = p & 3;
                    gp = bP + (size_t)(nt * 128 + row) * bStr + bOff + kc * 8;
                    d = smem_u32(base + MAT_A + row * ROWB + kc * 16);
                }
                CP16(d, gp);
            }
        }
        CPCOMMIT();   // empty trailing groups keep wait_group bookkeeping simple
    };

    auto compute_stage = [&](int buf) {
        uint32_t aBase = smem_u32(smem + buf * STAGE_B) + lr * ROWB + lkb;
        uint32_t bBase = aBase + MAT_A;
#pragma unroll
        for (int kk = 0; kk < 2; kk++) {
            uint32_t aF[4][4], bF[4][2];
#pragma unroll
            for (int im = 0; im < 4; im++)
                ldm4(aF[im], aBase + (wm * 64 + im * 16) * ROWB + kk * 32);
#pragma unroll
            for (int ig = 0; ig < 2; ig++) {
                uint32_t r[4];
                ldm4(r, bBase + (wn * 32 + ig * 16) * ROWB + kk * 32);
                bF[ig * 2][0] = r[0];     bF[ig * 2][1] = r[2];
                bF[ig * 2 + 1][0] = r[1]; bF[ig * 2 + 1][1] = r[3];
            }
#pragma unroll
            for (int im = 0; im < 4; im++)
#pragma unroll
                for (int iu = 0; iu < 4; iu++)
                    mma16816(acc[im][iu], aF[im], bF[iu]);
        }
    };

    issue_stage(0);
    issue_stage(1);
    issue_stage(2);
#pragma unroll 1
    for (int s = 0; s < NSTG; s++) {
        CPWAIT2();
        __syncthreads();
        issue_stage(s + 3);
        compute_stage(s & (NPIPE - 1));
    }

    // ---------------- fused gate epilogue ----------------
    const int g  = lane >> 2;
    const int t4 = lane & 3;
#pragma unroll
    for (int im = 0; im < 4; im++) {
#pragma unroll
        for (int iu = 0; iu < 4; iu++) {
            int np = nt * 128 + wn * 32 + iu * 8 + 2 * t4;
            float b0 = g_bil[np], b1 = g_bil[np + 1];
            float z0 = acc[im][iu][0] + b0;
            float z1 = acc[im][iu][1] + b1;
            float z2 = acc[im][iu][2] + b0;
            float z3 = acc[im][iu][3] + b1;
            float o0 = __shfl_xor_sync(0xFFFFFFFF, z0, 1);
            float o1 = __shfl_xor_sync(0xFFFFFFFF, z1, 1);
            float o2 = __shfl_xor_sync(0xFFFFFFFF, z2, 1);
            float o3 = __shfl_xor_sync(0xFFFFFFFF, z3, 1);
            if ((t4 & 1) == 0) {
                int j  = np >> 2;
                int m0 = mt * 128 + wm * 64 + im * 16 + g;
                gate_update(m0,     j, z0, z1, o0, o1, t, dst);
                gate_update(m0 + 8, j, z2, z3, o2, o3, t, dst);
            }
        }
    }
}

// ---------------- dense head ----------------
__global__ void dense_kernel(const float* __restrict__ Wd,
                             const float* __restrict__ bd,
                             float* __restrict__ out) {
    int m = blockIdx.x, o = threadIdx.x;
    if (o >= OUTsz) return;
    const float* hr = g_hflat + (size_t)m * Hsz;
    float acc = bd[o];
#pragma unroll 4
    for (int k = 0; k < Hsz; k++)
        acc = fmaf(hr[k], Wd[(size_t)k * OUTsz + o], acc);
    out[(size_t)m * OUTsz + o] = acc;
}

// ---------------------------------------------------------------------------
extern "C" void kernel_launch(void* const* d_in, const int* in_sizes, int n_in,
                              void* d_out, int out_size) {
    const float* x  = (const float*)d_in[0];
    const float* W  = (const float*)d_in[1];
    const float* U  = (const float*)d_in[2];
    const float* b  = (const float*)d_in[3];
    const float* Wd = (const float*)d_in[4];
    const float* bd = (const float*)d_in[5];
    float* out = (float*)d_out;

    static int attr_set = 0;
    if (!attr_set) {
        cudaFuncSetAttribute(step_kernel, cudaFuncAttributeMaxDynamicSharedMemorySize,
                             SMEM_TOTAL);
        attr_set = 1;
    }

    k_zero<<<(Bsz * Hsz + 255) / 256, 256>>>();
    k_repack_U<<<(1024 * 4096 + 255) / 256, 256>>>(U);
    k_repack_W<<<(96 * 4096 + 255) / 256, 256>>>(W);
    k_repack_x<<<(Bsz * Tsz * 96 + 255) / 256, 256>>>(x);
    k_repack_b<<<16, 256>>>(b);

    dim3 grid(32, 16);
    for (int t = 0; t < Tsz; t++)
        step_kernel<<<grid, 256, SMEM_TOTAL>>>(t);

    dense_kernel<<<Bsz, 32>>>(Wd, bd, out);
}

// round 10
// speedup vs baseline: 1.3224x; 1.0525x over previous
#include <cuda_runtime.h>
#include <cuda_fp16.h>
#include <cstdint>
#include <math.h>

#define Bsz 2048
#define Tsz 60
#define Fsz 89
#define Hsz 1024
#define OUTsz 30

#define NPAIR 18           // 16 pairs of 64K (h@U) + 2 pairs (x@W, padded 96->128)
#define ROWB 144           // smem row pitch: 64 fp16 (128B) + 16B pad (conflict-free)
#define MAT_A 18432        // 128 rows * 144
#define PAIR_B 36864       // A + B
#define NBUF 3
#define SMEM_TOTAL (NBUF * PAIR_B)   // 110592 -> 2 CTAs/SM (221 KB < 228 KB)

// ---------------- device globals (no runtime allocation) ----------------
__device__ __align__(16) __half g_UB[(size_t)4096 * 1024];      // [np][k], np = 4*j+gate
__device__ __align__(16) __half g_WB[(size_t)4096 * 128];       // [np][k], k padded to 128
__device__ __align__(16) __half g_xB[(size_t)2048 * 60 * 128];  // [m][t][128], padded
__device__ __align__(16) __half g_hB[2][(size_t)2048 * 1024];   // ping-pong [m][k]
__device__ float g_c[(size_t)2048 * 1024];
__device__ float g_hflat[(size_t)2048 * 1024];
__device__ float g_bil[4096];

// ---------------- PTX helpers (baseline ISA only) ----------------
__device__ __forceinline__ uint32_t smem_u32(const void* p) {
    uint32_t a;
    asm("{ .reg .u64 t; cvta.to.shared.u64 t, %1; cvt.u32.u64 %0, t; }" : "=r"(a) : "l"(p));
    return a;
}
#define CP16(dst, src) \
    asm volatile("cp.async.cg.shared.global [%0], [%1], 16;" :: "r"(dst), "l"(src))
#define CPCOMMIT() asm volatile("cp.async.commit_group;" ::: "memory")
#define CPWAIT1()  asm volatile("cp.async.wait_group 1;" ::: "memory")

__device__ __forceinline__ void ldm4(uint32_t* r, uint32_t addr) {
    asm volatile("ldmatrix.sync.aligned.m8n8.x4.shared.b16 {%0,%1,%2,%3}, [%4];"
        : "=r"(r[0]), "=r"(r[1]), "=r"(r[2]), "=r"(r[3]) : "r"(addr));
}
__device__ __forceinline__ void mma16816(float* d, const uint32_t* a, const uint32_t* b) {
    asm volatile(
        "mma.sync.aligned.m16n8k16.row.col.f32.f16.f16.f32 "
        "{%0,%1,%2,%3}, {%4,%5,%6,%7}, {%8,%9}, {%0,%1,%2,%3};"
        : "+f"(d[0]), "+f"(d[1]), "+f"(d[2]), "+f"(d[3])
        : "r"(a[0]), "r"(a[1]), "r"(a[2]), "r"(a[3]), "r"(b[0]), "r"(b[1]));
}

// ---------------- single merged init/repack kernel ----------------
#define SEG0 ((size_t)2048 * 1024)        // zero c, h
#define SEG1 ((size_t)1024 * 4096)        // repack U
#define SEG2 ((size_t)128 * 4096)         // repack W (padded K)
#define SEG3 ((size_t)2048 * 60 * 128)    // repack x (padded F)
#define SEG4 ((size_t)4096)               // repack bias
#define TOTI (SEG0 + SEG1 + SEG2 + SEG3 + SEG4)

__global__ void k_init(const float* __restrict__ x, const float* __restrict__ W,
                       const float* __restrict__ U, const float* __restrict__ b) {
    size_t i = (size_t)blockIdx.x * 256 + threadIdx.x;
    if (i < SEG0) {
        g_c[i] = 0.0f;
        g_hB[0][i] = __float2half(0.0f);
        return;
    }
    i -= SEG0;
    if (i < SEG1) {
        int k = (int)(i >> 12), c = (int)(i & 4095);
        int np = 4 * (c & 1023) + (c >> 10);
        g_UB[(size_t)np * 1024 + k] = __float2half(U[i]);
        return;
    }
    i -= SEG1;
    if (i < SEG2) {
        int k = (int)(i >> 12), c = (int)(i & 4095);
        float v = (k < Fsz) ? W[(size_t)k * 4096 + c] : 0.0f;
        int np = 4 * (c & 1023) + (c >> 10);
        g_WB[(size_t)np * 128 + k] = __float2half(v);
        return;
    }
    i -= SEG2;
    if (i < SEG3) {
        int k = (int)(i & 127);
        size_t mt_ = i >> 7;   // m*60 + t
        float v = (k < Fsz) ? x[mt_ * Fsz + k] : 0.0f;
        g_xB[i] = __float2half(v);
        return;
    }
    i -= SEG3;
    if (i < SEG4) {
        int c = (int)i;
        g_bil[4 * (c & 1023) + (c >> 10)] = b[c];
    }
}

// ---------------- LSTM gate update ----------------
__device__ __forceinline__ void gate_update(int m, int j, float zi, float zf,
                                            float zg, float zo, int t, int dst) {
    size_t idx = (size_t)m * Hsz + j;
    float ig = 1.0f / (1.0f + expf(-zi));
    float fg = 1.0f / (1.0f + expf(-zf));
    float og = 1.0f / (1.0f + expf(-zo));
    float c = fg * g_c[idx] + ig * fmaxf(zg, 0.0f);
    g_c[idx] = c;
    float h = og * fmaxf(c, 0.0f);
    if (t == Tsz - 1) g_hflat[idx] = h;
    else              g_hB[dst][idx] = __float2half(h);
}

// ---------------- per-timestep fused GEMM + gate kernel ----------------
// CTA tile 128(M) x 128(N), 8 warps (2x4), warp tile 64x32, fp16.
// K in 18 pairs of 64; 3 smem buffers; wait -> barrier -> issue -> compute.
__global__ __launch_bounds__(256, 2) void step_kernel(int t) {
    extern __shared__ __align__(128) char smem[];
    const int tid  = threadIdx.x;
    const int nt   = blockIdx.x;      // 0..31 (128 np-cols)
    const int mt   = blockIdx.y;      // 0..15 (128 rows)
    const int wid  = tid >> 5, lane = tid & 31;
    const int wm   = wid >> 2, wn = wid & 3;
    const int src  = t & 1, dst = src ^ 1;

    float acc[4][4][4];
#pragma unroll
    for (int a = 0; a < 4; a++)
#pragma unroll
        for (int b = 0; b < 4; b++)
#pragma unroll
            for (int c = 0; c < 4; c++) acc[a][b][c] = 0.0f;

    const int lr  = lane & 15;
    const int lkb = ((lane >> 4) & 1) * 16;

    // buffer index by pair: p % 3
    auto issue_pair = [&](int p, int buf) {
        if (p < NPAIR) {
            const __half *aP, *bP;
            int aStr, bStr; size_t aOff, bOff;
            if (p < 16) {
                aP = g_hB[src]; aStr = 1024; aOff = (size_t)64 * p;
                bP = g_UB;      bStr = 1024; bOff = (size_t)64 * p;
            } else {
                int i = p - 16;
                aP = g_xB; aStr = Tsz * 128; aOff = (size_t)t * 128 + 64 * i;
                bP = g_WB; bStr = 128;       bOff = (size_t)64 * i;
            }
            char* base = smem + buf * PAIR_B;
#pragma unroll
            for (int it = 0; it < 8; it++) {
                int q = it * 256 + tid;            // 2048 chunks of 16B
                const __half* gp;
                uint32_t d;
                if (q < 1024) {
                    int row = q >> 3, kc = q & 7;
                    gp = aP + (size_t)(mt * 128 + row) * aStr + aOff + kc * 8;
                    d = smem_u32(base + row * ROWB + kc * 16);
                } else {
                    int pq = q - 1024;
                    int row = pq >> 3, kc = pq & 7;
                    gp = bP + (size_t)(nt * 128 + row) * bStr + bOff + kc * 8;
                    d = smem_u32(base + MAT_A + row * ROWB + kc * 16);
                }
                CP16(d, gp);
            }
        }
        CPCOMMIT();   // empty trailing group keeps wait_group bookkeeping simple
    };

    auto compute_pair = [&](int buf) {
        uint32_t aBase = smem_u32(smem + buf * PAIR_B) + lr * ROWB + lkb;
        uint32_t bBase = aBase + MAT_A;
#pragma unroll
        for (int kk = 0; kk < 4; kk++) {
            uint32_t aF[4][4], bF[4][2];
#pragma unroll
            for (int im = 0; im < 4; im++)
                ldm4(aF[im], aBase + (wm * 64 + im * 16) * ROWB + kk * 32);
#pragma unroll
            for (int ig = 0; ig < 2; ig++) {
                uint32_t r[4];
                ldm4(r, bBase + (wn * 32 + ig * 16) * ROWB + kk * 32);
                bF[ig * 2][0] = r[0];     bF[ig * 2][1] = r[2];
                bF[ig * 2 + 1][0] = r[1]; bF[ig * 2 + 1][1] = r[3];
            }
#pragma unroll
            for (int im = 0; im < 4; im++)
#pragma unroll
                for (int iu = 0; iu < 4; iu++)
                    mma16816(acc[im][iu], aF[im], bF[iu]);
        }
    };

    // pair p lives in buffer p % 3
    issue_pair(0, 0);
    issue_pair(1, 1);
    int b0 = 0, b1 = 1, b2 = 2;   // buffers for pairs p, p+1, p+2
#pragma unroll 1
    for (int p = 0; p < NPAIR; p++) {
        CPWAIT1();                // this thread's group for pair p complete
        __syncthreads();          // => ALL threads' groups for pair p complete
        issue_pair(p + 2, b2);    // b2 last read at iter p-1, ordered by the barrier
        compute_pair(b0);
        int tmp = b0; b0 = b1; b1 = b2; b2 = tmp;
    }

    // ---------------- fused gate epilogue ----------------
    const int g  = lane >> 2;
    const int t4 = lane & 3;
#pragma unroll
    for (int im = 0; im < 4; im++) {
#pragma unroll
        for (int iu = 0; iu < 4; iu++) {
            int np = nt * 128 + wn * 32 + iu * 8 + 2 * t4;
            float b0f = g_bil[np], b1f = g_bil[np + 1];
            float z0 = acc[im][iu][0] + b0f;
            float z1 = acc[im][iu][1] + b1f;
            float z2 = acc[im][iu][2] + b0f;
            float z3 = acc[im][iu][3] + b1f;
            float o0 = __shfl_xor_sync(0xFFFFFFFF, z0, 1);
            float o1 = __shfl_xor_sync(0xFFFFFFFF, z1, 1);
            float o2 = __shfl_xor_sync(0xFFFFFFFF, z2, 1);
            float o3 = __shfl_xor_sync(0xFFFFFFFF, z3, 1);
            if ((t4 & 1) == 0) {
                int j  = np >> 2;
                int m0 = mt * 128 + wm * 64 + im * 16 + g;
                gate_update(m0,     j, z0, z1, o0, o1, t, dst);
                gate_update(m0 + 8, j, z2, z3, o2, o3, t, dst);
            }
        }
    }
}

// ---------------- dense head ----------------
__global__ void dense_kernel(const float* __restrict__ Wd,
                             const float* __restrict__ bd,
                             float* __restrict__ out) {
    int m = blockIdx.x, o = threadIdx.x;
    if (o >= OUTsz) return;
    const float* hr = g_hflat + (size_t)m * Hsz;
    float acc = bd[o];
#pragma unroll 4
    for (int k = 0; k < Hsz; k++)
        acc = fmaf(hr[k], Wd[(size_t)k * OUTsz + o], acc);
    out[(size_t)m * OUTsz + o] = acc;
}

// ---------------------------------------------------------------------------
extern "C" void kernel_launch(void* const* d_in, const int* in_sizes, int n_in,
                              void* d_out, int out_size) {
    const float* x  = (const float*)d_in[0];
    const float* W  = (const float*)d_in[1];
    const float* U  = (const float*)d_in[2];
    const float* b  = (const float*)d_in[3];
    const float* Wd = (const float*)d_in[4];
    const float* bd = (const float*)d_in[5];
    float* out = (float*)d_out;

    static int attr_set = 0;
    if (!attr_set) {
        cudaFuncSetAttribute(step_kernel, cudaFuncAttributeMaxDynamicSharedMemorySize,
                             SMEM_TOTAL);
        attr_set = 1;
    }

    k_init<<<(int)((TOTI + 255) / 256), 256>>>(x, W, U, b);

    dim3 grid(32, 16);
    for (int t = 0; t < Tsz; t++)
        step_kernel<<<grid, 256, SMEM_TOTAL>>>(t);

    dense_kernel<<<Bsz, 32>>>(Wd, bd, out);
}

// round 11
// speedup vs baseline: 1.3734x; 1.0386x over previous
#include <cuda_runtime.h>
#include <cuda_fp16.h>
#include <cstdint>
#include <math.h>

#define Bsz 2048
#define Tsz 60
#define Fsz 89
#define Hsz 1024
#define OUTsz 30

#define NPAIR 18           // 16 pairs of 64K (h@U) + 2 pairs (x@W, padded 96->128)
#define ROWB 144           // smem row pitch: 64 fp16 (128B) + 16B pad (conflict-free)
#define MAT_A 18432        // 128 rows * 144
#define PAIR_B 36864       // A + B
#define NBUF 3
#define SMEM_TOTAL (NBUF * PAIR_B)   // 110592 -> 2 CTAs/SM

// ---------------- device globals (no runtime allocation) ----------------
__device__ __align__(16) __half g_UB[(size_t)4096 * 1024];      // [np][k], np = 4*j+gate
__device__ __align__(16) __half g_WB[(size_t)4096 * 128];       // [np][k], k padded to 128
__device__ __align__(16) __half g_xB[(size_t)2048 * 60 * 128];  // [m][t][128], padded
__device__ __align__(16) __half g_hB[2][(size_t)2048 * 1024];   // ping-pong [m][k]
__device__ float g_c[(size_t)2048 * 1024];
__device__ float g_hflat[(size_t)2048 * 1024];
__device__ float g_bil[4096];

// ---------------- PTX helpers (baseline ISA only) ----------------
__device__ __forceinline__ uint32_t smem_u32(const void* p) {
    uint32_t a;
    asm("{ .reg .u64 t; cvta.to.shared.u64 t, %1; cvt.u32.u64 %0, t; }" : "=r"(a) : "l"(p));
    return a;
}
#define CP16(dst, src) \
    asm volatile("cp.async.cg.shared.global [%0], [%1], 16;" :: "r"(dst), "l"(src))
#define CPCOMMIT() asm volatile("cp.async.commit_group;" ::: "memory")
#define CPWAIT1()  asm volatile("cp.async.wait_group 1;" ::: "memory")

__device__ __forceinline__ void ldm4(uint32_t* r, uint32_t addr) {
    asm volatile("ldmatrix.sync.aligned.m8n8.x4.shared.b16 {%0,%1,%2,%3}, [%4];"
        : "=r"(r[0]), "=r"(r[1]), "=r"(r[2]), "=r"(r[3]) : "r"(addr));
}
__device__ __forceinline__ void mma16816(float* d, const uint32_t* a, const uint32_t* b) {
    asm volatile(
        "mma.sync.aligned.m16n8k16.row.col.f32.f16.f16.f32 "
        "{%0,%1,%2,%3}, {%4,%5,%6,%7}, {%8,%9}, {%0,%1,%2,%3};"
        : "+f"(d[0]), "+f"(d[1]), "+f"(d[2]), "+f"(d[3])
        : "r"(a[0]), "r"(a[1]), "r"(a[2]), "r"(a[3]), "r"(b[0]), "r"(b[1]));
}

// ---------------- single merged init/repack kernel ----------------
#define SEG0 ((size_t)2048 * 1024)        // zero c, h
#define SEG1 ((size_t)1024 * 4096)        // repack U
#define SEG2 ((size_t)128 * 4096)         // repack W (padded K)
#define SEG3 ((size_t)2048 * 60 * 128)    // repack x (padded F)
#define SEG4 ((size_t)4096)               // repack bias
#define TOTI (SEG0 + SEG1 + SEG2 + SEG3 + SEG4)

__global__ void k_init(const float* __restrict__ x, const float* __restrict__ W,
                       const float* __restrict__ U, const float* __restrict__ b) {
    size_t i = (size_t)blockIdx.x * 256 + threadIdx.x;
    if (i < SEG0) {
        g_c[i] = 0.0f;
        g_hB[0][i] = __float2half(0.0f);
        return;
    }
    i -= SEG0;
    if (i < SEG1) {
        int k = (int)(i >> 12), c = (int)(i & 4095);
        int np = 4 * (c & 1023) + (c >> 10);
        g_UB[(size_t)np * 1024 + k] = __float2half(U[i]);
        return;
    }
    i -= SEG1;
    if (i < SEG2) {
        int k = (int)(i >> 12), c = (int)(i & 4095);
        float v = (k < Fsz) ? W[(size_t)k * 4096 + c] : 0.0f;
        int np = 4 * (c & 1023) + (c >> 10);
        g_WB[(size_t)np * 128 + k] = __float2half(v);
        return;
    }
    i -= SEG2;
    if (i < SEG3) {
        int k = (int)(i & 127);
        size_t mt_ = i >> 7;   // m*60 + t
        float v = (k < Fsz) ? x[mt_ * Fsz + k] : 0.0f;
        g_xB[i] = __float2half(v);
        return;
    }
    i -= SEG3;
    if (i < SEG4) {
        int c = (int)i;
        g_bil[4 * (c & 1023) + (c >> 10)] = b[c];
    }
}

// ---------------- LSTM gate update ----------------
__device__ __forceinline__ void gate_update(int m, int j, float zi, float zf,
                                            float zg, float zo, int t, int dst) {
    size_t idx = (size_t)m * Hsz + j;
    float ig = 1.0f / (1.0f + expf(-zi));
    float fg = 1.0f / (1.0f + expf(-zf));
    float og = 1.0f / (1.0f + expf(-zo));
    float c = fg * g_c[idx] + ig * fmaxf(zg, 0.0f);
    g_c[idx] = c;
    float h = og * fmaxf(c, 0.0f);
    if (t == Tsz - 1) g_hflat[idx] = h;
    else              g_hB[dst][idx] = __float2half(h);
}

// ---------------- per-timestep fused GEMM + gate kernel ----------------
// CTA tile 128(M) x 128(N), 8 warps (2x4), warp tile 64x32, fp16.
// K in 18 pairs of 64; 3 buffers; wait -> barrier -> issue -> compute.
// B fragments loaded pair-wide up front; A ldmatrix overlaps HMMA across m-tiles.
__global__ __launch_bounds__(256, 2) void step_kernel(int t) {
    extern __shared__ __align__(128) char smem[];
    const int tid  = threadIdx.x;
    const int nt   = blockIdx.x;      // 0..31 (128 np-cols)
    const int mt   = blockIdx.y;      // 0..15 (128 rows)
    const int wid  = tid >> 5, lane = tid & 31;
    const int wm   = wid >> 2, wn = wid & 3;
    const int src  = t & 1, dst = src ^ 1;

    float acc[4][4][4];
#pragma unroll
    for (int a = 0; a < 4; a++)
#pragma unroll
        for (int b = 0; b < 4; b++)
#pragma unroll
            for (int c = 0; c < 4; c++) acc[a][b][c] = 0.0f;

    const int lr  = lane & 15;
    const int lkb = ((lane >> 4) & 1) * 16;
    const uint32_t smemBase = smem_u32(smem);

    // ---- hoisted per-thread load addressing ----
    const int rA = tid >> 3;          // 0..31: base row within the 128-row tile
    const int kc = tid & 7;           // 16B chunk within 64-element K pair
    const __half* pA[4];
    const __half* pB[4];
    uint32_t dA[4], dB[4];
#pragma unroll
    for (int it = 0; it < 4; it++) {
        int row = rA + 32 * it;
        pA[it] = g_hB[src] + (size_t)(mt * 128 + row) * 1024 + kc * 8;
        pB[it] = g_UB      + (size_t)(nt * 128 + row) * 1024 + kc * 8;
        dA[it] = row * ROWB + kc * 16;
        dB[it] = MAT_A + row * ROWB + kc * 16;
    }

    auto issue_pair = [&](int p, int buf) {
        if (p < NPAIR) {
            uint32_t sb = smemBase + buf * PAIR_B;
            if (p < 16) {
#pragma unroll
                for (int it = 0; it < 4; it++) {
                    CP16(sb + dA[it], pA[it]);
                    CP16(sb + dB[it], pB[it]);
                    pA[it] += 64;
                    pB[it] += 64;
                }
            } else {
                int i = p - 16;
#pragma unroll
                for (int it = 0; it < 4; it++) {
                    int row = rA + 32 * it;
                    const __half* ax = g_xB + (size_t)(mt * 128 + row) * (Tsz * 128)
                                     + (size_t)t * 128 + 64 * i + kc * 8;
                    const __half* bx = g_WB + (size_t)(nt * 128 + row) * 128
                                     + 64 * i + kc * 8;
                    CP16(sb + dA[it], ax);
                    CP16(sb + dB[it], bx);
                }
            }
        }
        CPCOMMIT();   // empty trailing group keeps wait_group bookkeeping simple
    };

    auto compute_pair = [&](int buf) {
        uint32_t aBase = smemBase + buf * PAIR_B + lr * ROWB + lkb;
        uint32_t bBase = aBase + MAT_A;
        // all B fragments for this pair up front (amortize the LDSM bubble once)
        uint32_t bF[4][4][2];   // [kk][iu][2]
#pragma unroll
        for (int kk = 0; kk < 4; kk++) {
#pragma unroll
            for (int ig = 0; ig < 2; ig++) {
                uint32_t r[4];
                ldm4(r, bBase + (wn * 32 + ig * 16) * ROWB + kk * 32);
                bF[kk][ig * 2][0] = r[0];     bF[kk][ig * 2][1] = r[2];
                bF[kk][ig * 2 + 1][0] = r[1]; bF[kk][ig * 2 + 1][1] = r[3];
            }
        }
        // m-tiles: A loads for im+1 are independent of HMMA for im
#pragma unroll
        for (int im = 0; im < 4; im++) {
            uint32_t aF[4][4];
#pragma unroll
            for (int kk = 0; kk < 4; kk++)
                ldm4(aF[kk], aBase + (wm * 64 + im * 16) * ROWB + kk * 32);
#pragma unroll
            for (int kk = 0; kk < 4; kk++)
#pragma unroll
                for (int iu = 0; iu < 4; iu++)
                    mma16816(acc[im][iu], aF[kk], bF[kk][iu]);
        }
    };

    // pair p lives in buffer p % 3
    issue_pair(0, 0);
    issue_pair(1, 1);
    int b0 = 0, b1 = 1, b2 = 2;
#pragma unroll 1
    for (int p = 0; p < NPAIR; p++) {
        CPWAIT1();                // this thread's group for pair p complete
        __syncthreads();          // => ALL threads' groups for pair p complete
        issue_pair(p + 2, b2);    // b2 last read at iter p-1, ordered by the barrier
        compute_pair(b0);
        int tmp = b0; b0 = b1; b1 = b2; b2 = tmp;
    }

    // ---------------- fused gate epilogue ----------------
    const int g  = lane >> 2;
    const int t4 = lane & 3;
#pragma unroll
    for (int im = 0; im < 4; im++) {
#pragma unroll
        for (int iu = 0; iu < 4; iu++) {
            int np = nt * 128 + wn * 32 + iu * 8 + 2 * t4;
            float b0f = g_bil[np], b1f = g_bil[np + 1];
            float z0 = acc[im][iu][0] + b0f;
            float z1 = acc[im][iu][1] + b1f;
            float z2 = acc[im][iu][2] + b0f;
            float z3 = acc[im][iu][3] + b1f;
            float o0 = __shfl_xor_sync(0xFFFFFFFF, z0, 1);
            float o1 = __shfl_xor_sync(0xFFFFFFFF, z1, 1);
            float o2 = __shfl_xor_sync(0xFFFFFFFF, z2, 1);
            float o3 = __shfl_xor_sync(0xFFFFFFFF, z3, 1);
            if ((t4 & 1) == 0) {
                int j  = np >> 2;
                int m0 = mt * 128 + wm * 64 + im * 16 + g;
                gate_update(m0,     j, z0, z1, o0, o1, t, dst);
                gate_update(m0 + 8, j, z2, z3, o2, o3, t, dst);
            }
        }
    }
}

// ---------------- dense head ----------------
__global__ void dense_kernel(const float* __restrict__ Wd,
                             const float* __restrict__ bd,
                             float* __restrict__ out) {
    int m = blockIdx.x, o = threadIdx.x;
    if (o >= OUTsz) return;
    const float* hr = g_hflat + (size_t)m * Hsz;
    float acc = bd[o];
#pragma unroll 4
    for (int k = 0; k < Hsz; k++)
        acc = fmaf(hr[k], Wd[(size_t)k * OUTsz + o], acc);
    out[(size_t)m * OUTsz + o] = acc;
}

// ---------------------------------------------------------------------------
extern "C" void kernel_launch(void* const* d_in, const int* in_sizes, int n_in,
                              void* d_out, int out_size) {
    const float* x  = (const float*)d_in[0];
    const float* W  = (const float*)d_in[1];
    const float* U  = (const float*)d_in[2];
    const float* b  = (const float*)d_in[3];
    const float* Wd = (const float*)d_in[4];
    const float* bd = (const float*)d_in[5];
    float* out = (float*)d_out;

    static int attr_set = 0;
    if (!attr_set) {
        cudaFuncSetAttribute(step_kernel, cudaFuncAttributeMaxDynamicSharedMemorySize,
                             SMEM_TOTAL);
        attr_set = 1;
    }

    k_init<<<(int)((TOTI + 255) / 256), 256>>>(x, W, U, b);

    dim3 grid(32, 16);
    for (int t = 0; t < Tsz; t++)
        step_kernel<<<grid, 256, SMEM_TOTAL>>>(t);

    dense_kernel<<<Bsz, 32>>>(Wd, bd, out);
}

// round 12
// speedup vs baseline: 1.4817x; 1.0788x over previous
#include <cuda_runtime.h>
#include <cuda_fp16.h>
#include <cstdint>
#include <math.h>

#define Bsz 2048
#define Tsz 60
#define Fsz 89
#define Hsz 1024
#define OUTsz 30

#define NPAIR 18           // 16 pairs of 64K (h@U) + 2 pairs (x@W, padded 96->128)
#define ROWB 144           // smem row pitch: 64 fp16 (128B) + 16B pad (conflict-free)
#define MAT_A 18432        // 128 rows * 144
#define PAIR_B 36864       // A + B
#define NBUF 3
#define SMEM_TOTAL (NBUF * PAIR_B)   // 110592 -> 2 CTAs/SM

// ---------------- device globals (no runtime allocation) ----------------
__device__ __align__(16) __half g_UB[(size_t)4096 * 1024];      // [np][k], np = 4*j+gate
__device__ __align__(16) __half g_WB[(size_t)4096 * 128];       // [np][k], k padded to 128
__device__ __align__(16) __half g_xB[(size_t)2048 * 60 * 128];  // [m][t][128], padded
__device__ __align__(16) __half g_hB[2][(size_t)2048 * 1024];   // ping-pong [m][k]
__device__ float g_c[(size_t)2048 * 1024];
__device__ float g_hflat[(size_t)2048 * 1024];
__device__ float g_bil[4096];

// ---------------- PTX helpers (baseline ISA only) ----------------
__device__ __forceinline__ uint32_t smem_u32(const void* p) {
    uint32_t a;
    asm("{ .reg .u64 t; cvta.to.shared.u64 t, %1; cvt.u32.u64 %0, t; }" : "=r"(a) : "l"(p));
    return a;
}
#define CP16(dst, src) \
    asm volatile("cp.async.cg.shared.global [%0], [%1], 16;" :: "r"(dst), "l"(src))
#define CPCOMMIT() asm volatile("cp.async.commit_group;" ::: "memory")
#define CPWAIT1()  asm volatile("cp.async.wait_group 1;" ::: "memory")

__device__ __forceinline__ void ldm4(uint32_t* r, uint32_t addr) {
    asm volatile("ldmatrix.sync.aligned.m8n8.x4.shared.b16 {%0,%1,%2,%3}, [%4];"
        : "=r"(r[0]), "=r"(r[1]), "=r"(r[2]), "=r"(r[3]) : "r"(addr));
}
__device__ __forceinline__ void mma16816(float* d, const uint32_t* a, const uint32_t* b) {
    asm volatile(
        "mma.sync.aligned.m16n8k16.row.col.f32.f16.f16.f32 "
        "{%0,%1,%2,%3}, {%4,%5,%6,%7}, {%8,%9}, {%0,%1,%2,%3};"
        : "+f"(d[0]), "+f"(d[1]), "+f"(d[2]), "+f"(d[3])
        : "r"(a[0]), "r"(a[1]), "r"(a[2]), "r"(a[3]), "r"(b[0]), "r"(b[1]));
}

// ---------------- single merged init/repack kernel ----------------
#define SEG0 ((size_t)2048 * 1024)        // zero c, h
#define SEG1 ((size_t)1024 * 4096)        // repack U
#define SEG2 ((size_t)128 * 4096)         // repack W (padded K)
#define SEG3 ((size_t)2048 * 60 * 128)    // repack x (padded F)
#define SEG4 ((size_t)4096)               // repack bias
#define TOTI (SEG0 + SEG1 + SEG2 + SEG3 + SEG4)

__global__ void k_init(const float* __restrict__ x, const float* __restrict__ W,
                       const float* __restrict__ U, const float* __restrict__ b) {
    size_t i = (size_t)blockIdx.x * 256 + threadIdx.x;
    if (i < SEG0) {
        g_c[i] = 0.0f;
        g_hB[0][i] = __float2half(0.0f);
        return;
    }
    i -= SEG0;
    if (i < SEG1) {
        int k = (int)(i >> 12), c = (int)(i & 4095);
        int np = 4 * (c & 1023) + (c >> 10);
        g_UB[(size_t)np * 1024 + k] = __float2half(U[i]);
        return;
    }
    i -= SEG1;
    if (i < SEG2) {
        int k = (int)(i >> 12), c = (int)(i & 4095);
        float v = (k < Fsz) ? W[(size_t)k * 4096 + c] : 0.0f;
        int np = 4 * (c & 1023) + (c >> 10);
        g_WB[(size_t)np * 128 + k] = __float2half(v);
        return;
    }
    i -= SEG2;
    if (i < SEG3) {
        int k = (int)(i & 127);
        size_t mt_ = i >> 7;   // m*60 + t
        float v = (k < Fsz) ? x[mt_ * Fsz + k] : 0.0f;
        g_xB[i] = __float2half(v);
        return;
    }
    i -= SEG3;
    if (i < SEG4) {
        int c = (int)i;
        g_bil[4 * (c & 1023) + (c >> 10)] = b[c];
    }
}

// ---------------- LSTM gate update ----------------
__device__ __forceinline__ void gate_update(int m, int j, float zi, float zf,
                                            float zg, float zo, int t, int dst) {
    size_t idx = (size_t)m * Hsz + j;
    float ig = 1.0f / (1.0f + expf(-zi));
    float fg = 1.0f / (1.0f + expf(-zf));
    float og = 1.0f / (1.0f + expf(-zo));
    float c = fg * g_c[idx] + ig * fmaxf(zg, 0.0f);
    g_c[idx] = c;
    float h = og * fmaxf(c, 0.0f);
    if (t == Tsz - 1) g_hflat[idx] = h;
    else              g_hB[dst][idx] = __float2half(h);
}

// ---------------- per-timestep fused GEMM + gate kernel ----------------
// CTA tile 128(M) x 128(N), 512 threads, 16 warps (4x4), warp tile 32x32, fp16.
// K in 18 pairs of 64; 3 buffers; wait -> barrier -> issue -> compute.
// 2 CTAs/SM (64 regs/thread) => 32 warps/SM for latency hiding.
__global__ __launch_bounds__(512, 2) void step_kernel(int t) {
    extern __shared__ __align__(128) char smem[];
    const int tid  = threadIdx.x;
    const int nt   = blockIdx.x;      // 0..31 (128 np-cols)
    const int mt   = blockIdx.y;      // 0..15 (128 rows)
    const int wid  = tid >> 5, lane = tid & 31;
    const int wm   = wid >> 2, wn = wid & 3;
    const int src  = t & 1, dst = src ^ 1;

    float acc[2][4][4];
#pragma unroll
    for (int a = 0; a < 2; a++)
#pragma unroll
        for (int b = 0; b < 4; b++)
#pragma unroll
            for (int c = 0; c < 4; c++) acc[a][b][c] = 0.0f;

    const int lr  = lane & 15;
    const int lkb = ((lane >> 4) & 1) * 16;
    const uint32_t smemBase = smem_u32(smem);

    // per-thread load mapping: 2048 chunks of 16B, 4 per thread
    const int rA = tid >> 3;          // 0..63: row pair index
    const int kc = tid & 7;           // 16B chunk within 64-elem K

    auto issue_pair = [&](int p, int buf) {
        if (p < NPAIR) {
            uint32_t sb = smemBase + buf * PAIR_B;
            if (p < 16) {
                const __half* aP = g_hB[src];
                size_t off = (size_t)64 * p + kc * 8;
#pragma unroll
                for (int it = 0; it < 2; it++) {
                    int row = rA + 64 * it;
                    CP16(sb + row * ROWB + kc * 16,
                         aP + (size_t)(mt * 128 + row) * 1024 + off);
                    CP16(sb + MAT_A + row * ROWB + kc * 16,
                         g_UB + (size_t)(nt * 128 + row) * 1024 + off);
                }
            } else {
                int i = p - 16;
#pragma unroll
                for (int it = 0; it < 2; it++) {
                    int row = rA + 64 * it;
                    CP16(sb + row * ROWB + kc * 16,
                         g_xB + (size_t)(mt * 128 + row) * (Tsz * 128)
                              + (size_t)t * 128 + 64 * i + kc * 8);
                    CP16(sb + MAT_A + row * ROWB + kc * 16,
                         g_WB + (size_t)(nt * 128 + row) * 128 + 64 * i + kc * 8);
                }
            }
        }
        CPCOMMIT();   // empty trailing group keeps wait_group bookkeeping simple
    };

    auto compute_pair = [&](int buf) {
        uint32_t aBase = smemBase + buf * PAIR_B + lr * ROWB + lkb
                       + (wm * 32) * ROWB;
        uint32_t bBase = smemBase + buf * PAIR_B + MAT_A + lr * ROWB + lkb
                       + (wn * 32) * ROWB;
#pragma unroll
        for (int kk = 0; kk < 4; kk++) {
            uint32_t aF[2][4], bF[4][2];
#pragma unroll
            for (int im = 0; im < 2; im++)
                ldm4(aF[im], aBase + im * 16 * ROWB + kk * 32);
#pragma unroll
            for (int ig = 0; ig < 2; ig++) {
                uint32_t r[4];
                ldm4(r, bBase + ig * 16 * ROWB + kk * 32);
                bF[ig * 2][0] = r[0];     bF[ig * 2][1] = r[2];
                bF[ig * 2 + 1][0] = r[1]; bF[ig * 2 + 1][1] = r[3];
            }
#pragma unroll
            for (int im = 0; im < 2; im++)
#pragma unroll
                for (int iu = 0; iu < 4; iu++)
                    mma16816(acc[im][iu], aF[im], bF[iu]);
        }
    };

    // pair p lives in buffer p % 3
    issue_pair(0, 0);
    issue_pair(1, 1);
    int b0 = 0, b1 = 1, b2 = 2;
#pragma unroll 1
    for (int p = 0; p < NPAIR; p++) {
        CPWAIT1();                // this thread's group for pair p complete
        __syncthreads();          // => ALL threads' groups for pair p complete
        issue_pair(p + 2, b2);    // b2 last read at iter p-1, ordered by the barrier
        compute_pair(b0);
        int tmp = b0; b0 = b1; b1 = b2; b2 = tmp;
    }

    // ---------------- fused gate epilogue ----------------
    const int g  = lane >> 2;
    const int t4 = lane & 3;
#pragma unroll
    for (int im = 0; im < 2; im++) {
#pragma unroll
        for (int iu = 0; iu < 4; iu++) {
            int np = nt * 128 + wn * 32 + iu * 8 + 2 * t4;
            float b0f = g_bil[np], b1f = g_bil[np + 1];
            float z0 = acc[im][iu][0] + b0f;
            float z1 = acc[im][iu][1] + b1f;
            float z2 = acc[im][iu][2] + b0f;
            float z3 = acc[im][iu][3] + b1f;
            float o0 = __shfl_xor_sync(0xFFFFFFFF, z0, 1);
            float o1 = __shfl_xor_sync(0xFFFFFFFF, z1, 1);
            float o2 = __shfl_xor_sync(0xFFFFFFFF, z2, 1);
            float o3 = __shfl_xor_sync(0xFFFFFFFF, z3, 1);
            if ((t4 & 1) == 0) {
                int j  = np >> 2;
                int m0 = mt * 128 + wm * 32 + im * 16 + g;
                gate_update(m0,     j, z0, z1, o0, o1, t, dst);
                gate_update(m0 + 8, j, z2, z3, o2, o3, t, dst);
            }
        }
    }
}

// ---------------- dense head ----------------
__global__ void dense_kernel(const float* __restrict__ Wd,
                             const float* __restrict__ bd,
                             float* __restrict__ out) {
    int m = blockIdx.x, o = threadIdx.x;
    if (o >= OUTsz) return;
    const float* hr = g_hflat + (size_t)m * Hsz;
    float acc = bd[o];
#pragma unroll 4
    for (int k = 0; k < Hsz; k++)
        acc = fmaf(hr[k], Wd[(size_t)k * OUTsz + o], acc);
    out[(size_t)m * OUTsz + o] = acc;
}

// ---------------------------------------------------------------------------
extern "C" void kernel_launch(void* const* d_in, const int* in_sizes, int n_in,
                              void* d_out, int out_size) {
    const float* x  = (const float*)d_in[0];
    const float* W  = (const float*)d_in[1];
    const float* U  = (const float*)d_in[2];
    const float* b  = (const float*)d_in[3];
    const float* Wd = (const float*)d_in[4];
    const float* bd = (const float*)d_in[5];
    float* out = (float*)d_out;

    static int attr_set = 0;
    if (!attr_set) {
        cudaFuncSetAttribute(step_kernel, cudaFuncAttributeMaxDynamicSharedMemorySize,
                             SMEM_TOTAL);
        attr_set = 1;
    }

    k_init<<<(int)((TOTI + 255) / 256), 256>>>(x, W, U, b);

    dim3 grid(32, 16);
    for (int t = 0; t < Tsz; t++)
        step_kernel<<<grid, 512, SMEM_TOTAL>>>(t);

    dense_kernel<<<Bsz, 32>>>(Wd, bd, out);
}

// round 13
// speedup vs baseline: 1.6020x; 1.0812x over previous
#include <cuda_runtime.h>
#include <cuda_fp16.h>
#include <cstdint>
#include <math.h>

#define Bsz 2048
#define Tsz 60
#define Fsz 89
#define Hsz 1024
#define OUTsz 30

#define NPAIR 18           // 16 pairs of 64K (h@U) + 2 pairs (x@W, padded 96->128)
#define ROWB 144           // smem row pitch: 64 fp16 (128B) + 16B pad (conflict-free)
#define MAT_A 18432        // 128 rows * 144
#define PAIR_B 36864       // A + B
#define NBUF 3
#define SMEM_TOTAL (NBUF * PAIR_B)   // 110592 -> 2 CTAs/SM

// ---------------- device globals (no runtime allocation) ----------------
__device__ __align__(16) __half g_UB[(size_t)4096 * 1024];      // [np][k], np = 4*j+gate
__device__ __align__(16) __half g_WB[(size_t)4096 * 128];       // [np][k], k padded to 128
__device__ __align__(16) __half g_xB[(size_t)2048 * 60 * 128];  // [m][t][128], padded
__device__ __align__(16) __half g_hB[2][(size_t)2048 * 1024];   // ping-pong [m][k]
__device__ float g_c[(size_t)2048 * 1024];
__device__ float g_hflat[(size_t)2048 * 1024];
__device__ float g_bil[4096];

// ---------------- PTX helpers (baseline ISA only) ----------------
__device__ __forceinline__ uint32_t smem_u32(const void* p) {
    uint32_t a;
    asm("{ .reg .u64 t; cvta.to.shared.u64 t, %1; cvt.u32.u64 %0, t; }" : "=r"(a) : "l"(p));
    return a;
}
#define CP16(dst, src) \
    asm volatile("cp.async.cg.shared.global [%0], [%1], 16;" :: "r"(dst), "l"(src))
#define CPCOMMIT() asm volatile("cp.async.commit_group;" ::: "memory")
#define CPWAIT1()  asm volatile("cp.async.wait_group 1;" ::: "memory")

__device__ __forceinline__ void ldm4(uint32_t* r, uint32_t addr) {
    asm volatile("ldmatrix.sync.aligned.m8n8.x4.shared.b16 {%0,%1,%2,%3}, [%4];"
        : "=r"(r[0]), "=r"(r[1]), "=r"(r[2]), "=r"(r[3]) : "r"(addr));
}
__device__ __forceinline__ void mma16816(float* d, const uint32_t* a, const uint32_t* b) {
    asm volatile(
        "mma.sync.aligned.m16n8k16.row.col.f32.f16.f16.f32 "
        "{%0,%1,%2,%3}, {%4,%5,%6,%7}, {%8,%9}, {%0,%1,%2,%3};"
        : "+f"(d[0]), "+f"(d[1]), "+f"(d[2]), "+f"(d[3])
        : "r"(a[0]), "r"(a[1]), "r"(a[2]), "r"(a[3]), "r"(b[0]), "r"(b[1]));
}

// fast sigmoid: rcp.approx(1 + 2^(-x*log2(e)))  — 2 MUFU + 2 FLOP
__device__ __forceinline__ float fsig(float x) {
    float e, r;
    asm("ex2.approx.f32 %0, %1;" : "=f"(e) : "f"(-1.4426950408889634f * x));
    asm("rcp.approx.f32 %0, %1;" : "=f"(r) : "f"(1.0f + e));
    return r;
}

// ---------------- single merged init/repack kernel ----------------
#define SEG0 ((size_t)2048 * 1024)        // zero c, h
#define SEG1 ((size_t)1024 * 4096)        // repack U
#define SEG2 ((size_t)128 * 4096)         // repack W (padded K)
#define SEG3 ((size_t)2048 * 60 * 128)    // repack x (padded F)
#define SEG4 ((size_t)4096)               // repack bias
#define TOTI (SEG0 + SEG1 + SEG2 + SEG3 + SEG4)

__global__ void k_init(const float* __restrict__ x, const float* __restrict__ W,
                       const float* __restrict__ U, const float* __restrict__ b) {
    size_t i = (size_t)blockIdx.x * 256 + threadIdx.x;
    if (i < SEG0) {
        g_c[i] = 0.0f;
        g_hB[0][i] = __float2half(0.0f);
        return;
    }
    i -= SEG0;
    if (i < SEG1) {
        int k = (int)(i >> 12), c = (int)(i & 4095);
        int np = 4 * (c & 1023) + (c >> 10);
        g_UB[(size_t)np * 1024 + k] = __float2half(U[i]);
        return;
    }
    i -= SEG1;
    if (i < SEG2) {
        int k = (int)(i >> 12), c = (int)(i & 4095);
        float v = (k < Fsz) ? W[(size_t)k * 4096 + c] : 0.0f;
        int np = 4 * (c & 1023) + (c >> 10);
        g_WB[(size_t)np * 128 + k] = __float2half(v);
        return;
    }
    i -= SEG2;
    if (i < SEG3) {
        int k = (int)(i & 127);
        size_t mt_ = i >> 7;   // m*60 + t
        float v = (k < Fsz) ? x[mt_ * Fsz + k] : 0.0f;
        g_xB[i] = __float2half(v);
        return;
    }
    i -= SEG3;
    if (i < SEG4) {
        int c = (int)i;
        g_bil[4 * (c & 1023) + (c >> 10)] = b[c];
    }
}

// ---------------- LSTM gate update ----------------
__device__ __forceinline__ void gate_update(int m, int j, float zi, float zf,
                                            float zg, float zo, int t, int dst) {
    size_t idx = (size_t)m * Hsz + j;
    float ig = fsig(zi);
    float fg = fsig(zf);
    float og = fsig(zo);
    float c = fg * g_c[idx] + ig * fmaxf(zg, 0.0f);
    g_c[idx] = c;
    float h = og * fmaxf(c, 0.0f);
    if (t == Tsz - 1) g_hflat[idx] = h;
    else              g_hB[dst][idx] = __float2half(h);
}

// ---------------- per-timestep fused GEMM + gate kernel ----------------
// CTA tile 128(M) x 128(N), 512 threads, 16 warps (4x4), warp tile 32x32, fp16.
// K in 18 pairs of 64; 3 buffers; wait -> barrier -> issue -> compute.
// 2 CTAs/SM (64 regs/thread) => 32 warps/SM for latency hiding.
__global__ __launch_bounds__(512, 2) void step_kernel(int t) {
    extern __shared__ __align__(128) char smem[];
    const int tid  = threadIdx.x;
    const int nt   = blockIdx.x;      // 0..31 (128 np-cols)
    const int mt   = blockIdx.y;      // 0..15 (128 rows)
    const int wid  = tid >> 5, lane = tid & 31;
    const int wm   = wid >> 2, wn = wid & 3;
    const int src  = t & 1, dst = src ^ 1;

    float acc[2][4][4];
#pragma unroll
    for (int a = 0; a < 2; a++)
#pragma unroll
        for (int b = 0; b < 4; b++)
#pragma unroll
            for (int c = 0; c < 4; c++) acc[a][b][c] = 0.0f;

    const int lr  = lane & 15;
    const int lkb = ((lane >> 4) & 1) * 16;
    const uint32_t smemBase = smem_u32(smem);

    // per-thread load mapping: 2048 chunks of 16B, 4 per thread
    const int rA = tid >> 3;          // 0..63: row pair index
    const int kc = tid & 7;           // 16B chunk within 64-elem K

    auto issue_pair = [&](int p, int buf) {
        if (p < NPAIR) {
            uint32_t sb = smemBase + buf * PAIR_B;
            if (p < 16) {
                const __half* aP = g_hB[src];
                size_t off = (size_t)64 * p + kc * 8;
#pragma unroll
                for (int it = 0; it < 2; it++) {
                    int row = rA + 64 * it;
                    CP16(sb + row * ROWB + kc * 16,
                         aP + (size_t)(mt * 128 + row) * 1024 + off);
                    CP16(sb + MAT_A + row * ROWB + kc * 16,
                         g_UB + (size_t)(nt * 128 + row) * 1024 + off);
                }
            } else {
                int i = p - 16;
#pragma unroll
                for (int it = 0; it < 2; it++) {
                    int row = rA + 64 * it;
                    CP16(sb + row * ROWB + kc * 16,
                         g_xB + (size_t)(mt * 128 + row) * (Tsz * 128)
                              + (size_t)t * 128 + 64 * i + kc * 8);
                    CP16(sb + MAT_A + row * ROWB + kc * 16,
                         g_WB + (size_t)(nt * 128 + row) * 128 + 64 * i + kc * 8);
                }
            }
        }
        CPCOMMIT();   // empty trailing group keeps wait_group bookkeeping simple
    };

    auto compute_pair = [&](int buf) {
        uint32_t aBase = smemBase + buf * PAIR_B + lr * ROWB + lkb
                       + (wm * 32) * ROWB;
        uint32_t bBase = smemBase + buf * PAIR_B + MAT_A + lr * ROWB + lkb
                       + (wn * 32) * ROWB;
#pragma unroll
        for (int kk = 0; kk < 4; kk++) {
            uint32_t aF[2][4], bF[4][2];
#pragma unroll
            for (int im = 0; im < 2; im++)
                ldm4(aF[im], aBase + im * 16 * ROWB + kk * 32);
#pragma unroll
            for (int ig = 0; ig < 2; ig++) {
                uint32_t r[4];
                ldm4(r, bBase + ig * 16 * ROWB + kk * 32);
                bF[ig * 2][0] = r[0];     bF[ig * 2][1] = r[2];
                bF[ig * 2 + 1][0] = r[1]; bF[ig * 2 + 1][1] = r[3];
            }
#pragma unroll
            for (int im = 0; im < 2; im++)
#pragma unroll
                for (int iu = 0; iu < 4; iu++)
                    mma16816(acc[im][iu], aF[im], bF[iu]);
        }
    };

    // pair p lives in buffer p % 3
    issue_pair(0, 0);
    issue_pair(1, 1);
    int b0 = 0, b1 = 1, b2 = 2;
#pragma unroll 1
    for (int p = 0; p < NPAIR; p++) {
        CPWAIT1();                // this thread's group for pair p complete
        __syncthreads();          // => ALL threads' groups for pair p complete
        issue_pair(p + 2, b2);    // b2 last read at iter p-1, ordered by the barrier
        compute_pair(b0);
        int tmp = b0; b0 = b1; b1 = b2; b2 = tmp;
    }

    // ---------------- fused gate epilogue ----------------
    const int g  = lane >> 2;
    const int t4 = lane & 3;
#pragma unroll
    for (int im = 0; im < 2; im++) {
#pragma unroll
        for (int iu = 0; iu < 4; iu++) {
            int np = nt * 128 + wn * 32 + iu * 8 + 2 * t4;
            float b0f = g_bil[np], b1f = g_bil[np + 1];
            float z0 = acc[im][iu][0] + b0f;
            float z1 = acc[im][iu][1] + b1f;
            float z2 = acc[im][iu][2] + b0f;
            float z3 = acc[im][iu][3] + b1f;
            float o0 = __shfl_xor_sync(0xFFFFFFFF, z0, 1);
            float o1 = __shfl_xor_sync(0xFFFFFFFF, z1, 1);
            float o2 = __shfl_xor_sync(0xFFFFFFFF, z2, 1);
            float o3 = __shfl_xor_sync(0xFFFFFFFF, z3, 1);
            if ((t4 & 1) == 0) {
                int j  = np >> 2;
                int m0 = mt * 128 + wm * 32 + im * 16 + g;
                gate_update(m0,     j, z0, z1, o0, o1, t, dst);
                gate_update(m0 + 8, j, z2, z3, o2, o3, t, dst);
            }
        }
    }
}

// ---------------- dense head ----------------
__global__ void dense_kernel(const float* __restrict__ Wd,
                             const float* __restrict__ bd,
                             float* __restrict__ out) {
    int m = blockIdx.x, o = threadIdx.x;
    if (o >= OUTsz) return;
    const float* hr = g_hflat + (size_t)m * Hsz;
    float acc = bd[o];
#pragma unroll 4
    for (int k = 0; k < Hsz; k++)
        acc = fmaf(hr[k], Wd[(size_t)k * OUTsz + o], acc);
    out[(size_t)m * OUTsz + o] = acc;
}

// ---------------------------------------------------------------------------
extern "C" void kernel_launch(void* const* d_in, const int* in_sizes, int n_in,
                              void* d_out, int out_size) {
    const float* x  = (const float*)d_in[0];
    const float* W  = (const float*)d_in[1];
    const float* U  = (const float*)d_in[2];
    const float* b  = (const float*)d_in[3];
    const float* Wd = (const float*)d_in[4];
    const float* bd = (const float*)d_in[5];
    float* out = (float*)d_out;

    static int attr_set = 0;
    if (!attr_set) {
        cudaFuncSetAttribute(step_kernel, cudaFuncAttributeMaxDynamicSharedMemorySize,
                             SMEM_TOTAL);
        attr_set = 1;
    }

    k_init<<<(int)((TOTI + 255) / 256), 256>>>(x, W, U, b);

    dim3 grid(32, 16);
    for (int t = 0; t < Tsz; t++)
        step_kernel<<<grid, 512, SMEM_TOTAL>>>(t);

    dense_kernel<<<Bsz, 32>>>(Wd, bd, out);
}

// round 14
// speedup vs baseline: 1.8055x; 1.1270x over previous
#include <cuda_runtime.h>
#include <cuda_fp16.h>
#include <cstdint>
#include <math.h>

#define Bsz 2048
#define Tsz 60
#define Fsz 89
#define Hsz 1024
#define OUTsz 30

#define NPAIR 18           // 16 pairs of 64K (h@U) + 2 pairs (x@W, padded 96->128)
#define ROWB 144           // smem row pitch: 64 fp16 (128B) + 16B pad (conflict-free)
#define MAT_A 18432        // 128 rows * 144
#define PAIR_B 36864       // A + B
#define NBUF 3
#define SMEM_TOTAL (NBUF * PAIR_B)   // 110592 -> 2 CTAs/SM

// ---------------- device globals (no runtime allocation) ----------------
__device__ __align__(16) __half g_UB[(size_t)4096 * 1024];      // [np][k], np = 4*j+gate
__device__ __align__(16) __half g_WB[(size_t)4096 * 128];       // [np][k], k padded to 128
__device__ __align__(16) __half g_xB[(size_t)2048 * 60 * 128];  // [m][t][128], padded
__device__ __align__(16) __half g_hB[2][(size_t)2048 * 1024];   // ping-pong [m][k]
__device__ __align__(16) float g_cblk[(size_t)512 * 4096];      // c, CTA-blocked [cta][128][32]
__device__ float g_hflat[(size_t)2048 * 1024];
__device__ float g_bil[4096];

// ---------------- PTX helpers (baseline ISA only) ----------------
__device__ __forceinline__ uint32_t smem_u32(const void* p) {
    uint32_t a;
    asm("{ .reg .u64 t; cvta.to.shared.u64 t, %1; cvt.u32.u64 %0, t; }" : "=r"(a) : "l"(p));
    return a;
}
#define CP16(dst, src) \
    asm volatile("cp.async.cg.shared.global [%0], [%1], 16;" :: "r"(dst), "l"(src))
#define CP16O(dst, src, off) \
    asm volatile("cp.async.cg.shared.global [%0], [%1+%2], 16;" :: "r"(dst), "l"(src), "n"(off))
#define CPCOMMIT() asm volatile("cp.async.commit_group;" ::: "memory")
#define CPWAIT1()  asm volatile("cp.async.wait_group 1;" ::: "memory")
#define CPWAIT0()  asm volatile("cp.async.wait_group 0;" ::: "memory")

__device__ __forceinline__ void ldm4(uint32_t* r, uint32_t addr) {
    asm volatile("ldmatrix.sync.aligned.m8n8.x4.shared.b16 {%0,%1,%2,%3}, [%4];"
        : "=r"(r[0]), "=r"(r[1]), "=r"(r[2]), "=r"(r[3]) : "r"(addr));
}
__device__ __forceinline__ void mma16816(float* d, const uint32_t* a, const uint32_t* b) {
    asm volatile(
        "mma.sync.aligned.m16n8k16.row.col.f32.f16.f16.f32 "
        "{%0,%1,%2,%3}, {%4,%5,%6,%7}, {%8,%9}, {%0,%1,%2,%3};"
        : "+f"(d[0]), "+f"(d[1]), "+f"(d[2]), "+f"(d[3])
        : "r"(a[0]), "r"(a[1]), "r"(a[2]), "r"(a[3]), "r"(b[0]), "r"(b[1]));
}

// fast sigmoid: rcp.approx(1 + 2^(-x*log2(e)))
__device__ __forceinline__ float fsig(float x) {
    float e, r;
    asm("ex2.approx.f32 %0, %1;" : "=f"(e) : "f"(-1.4426950408889634f * x));
    asm("rcp.approx.f32 %0, %1;" : "=f"(r) : "f"(1.0f + e));
    return r;
}

// ---------------- single merged init/repack kernel ----------------
#define SEG0 ((size_t)2048 * 1024)        // zero cblk, h
#define SEG1 ((size_t)1024 * 4096)        // repack U
#define SEG2 ((size_t)128 * 4096)         // repack W (padded K)
#define SEG3 ((size_t)2048 * 60 * 128)    // repack x (padded F)
#define SEG4 ((size_t)4096)               // repack bias
#define TOTI (SEG0 + SEG1 + SEG2 + SEG3 + SEG4)

__global__ void k_init(const float* __restrict__ x, const float* __restrict__ W,
                       const float* __restrict__ U, const float* __restrict__ b) {
    size_t i = (size_t)blockIdx.x * 256 + threadIdx.x;
    if (i < SEG0) {
        g_cblk[i] = 0.0f;
        g_hB[0][i] = __float2half(0.0f);
        return;
    }
    i -= SEG0;
    if (i < SEG1) {
        int k = (int)(i >> 12), c = (int)(i & 4095);
        int np = 4 * (c & 1023) + (c >> 10);
        g_UB[(size_t)np * 1024 + k] = __float2half(U[i]);
        return;
    }
    i -= SEG1;
    if (i < SEG2) {
        int k = (int)(i >> 12), c = (int)(i & 4095);
        float v = (k < Fsz) ? W[(size_t)k * 4096 + c] : 0.0f;
        int np = 4 * (c & 1023) + (c >> 10);
        g_WB[(size_t)np * 128 + k] = __float2half(v);
        return;
    }
    i -= SEG2;
    if (i < SEG3) {
        int k = (int)(i & 127);
        size_t mt_ = i >> 7;   // m*60 + t
        float v = (k < Fsz) ? x[mt_ * Fsz + k] : 0.0f;
        g_xB[i] = __float2half(v);
        return;
    }
    i -= SEG3;
    if (i < SEG4) {
        int c = (int)i;
        g_bil[4 * (c & 1023) + (c >> 10)] = b[c];
    }
}

// ---------------- per-timestep fused GEMM + gate kernel ----------------
// CTA tile 128(M) x 128(N), 512 threads, 16 warps (4x4), warp tile 32x32, fp16.
// K in 18 pairs of 64; 3 buffers; wait -> barrier -> issue -> compute.
// Running pointers + cp.async immediate offsets; smem-staged epilogue.
__global__ __launch_bounds__(512, 2) void step_kernel(int t) {
    extern __shared__ __align__(128) char smem[];
    const int tid  = threadIdx.x;
    const int nt   = blockIdx.x;      // 0..31 (128 np-cols)
    const int mt   = blockIdx.y;      // 0..15 (128 rows)
    const int wid  = tid >> 5, lane = tid & 31;
    const int wm   = wid >> 2, wn = wid & 3;
    const int src  = t & 1, dst = src ^ 1;

    float acc[2][4][4];
#pragma unroll
    for (int a = 0; a < 2; a++)
#pragma unroll
        for (int b = 0; b < 4; b++)
#pragma unroll
            for (int c = 0; c < 4; c++) acc[a][b][c] = 0.0f;

    const int lr  = lane & 15;
    const int lkb = ((lane >> 4) & 1) * 16;
    const uint32_t smemBase = smem_u32(smem);

    // ---- hoisted per-thread load addressing ----
    const int rA = tid >> 3;          // 0..63: row index
    const int kc = tid & 7;           // 16B chunk within 64-elem K
    const uint32_t dA0 = rA * ROWB + kc * 16;       // smem dst, it=0
    const uint32_t dB0 = MAT_A + dA0;
    // running global pointers (advance +128B per pair); it=1 via +131072B imm
    const char* pA = (const char*)(g_hB[src] + (size_t)(mt * 128 + rA) * 1024 + kc * 8);
    const char* pB = (const char*)(g_UB      + (size_t)(nt * 128 + rA) * 1024 + kc * 8);

    auto issue_pair = [&](int p, int buf) {
        if (p < NPAIR) {
            uint32_t sb = smemBase + buf * PAIR_B;
            if (p < 16) {
                CP16O(sb + dA0,        pA, 0);
                CP16O(sb + dA0 + 9216, pA, 131072);   // +64 rows
                CP16O(sb + dB0,        pB, 0);
                CP16O(sb + dB0 + 9216, pB, 131072);
                pA += 128;                            // +64 halves of K
                pB += 128;
            } else {
                int i = p - 16;
#pragma unroll
                for (int it = 0; it < 2; it++) {
                    int row = rA + 64 * it;
                    CP16(sb + dA0 + it * 9216,
                         g_xB + (size_t)(mt * 128 + row) * (Tsz * 128)
                              + (size_t)t * 128 + 64 * i + kc * 8);
                    CP16(sb + dB0 + it * 9216,
                         g_WB + (size_t)(nt * 128 + row) * 128 + 64 * i + kc * 8);
                }
            }
        }
        CPCOMMIT();   // empty trailing group keeps wait_group bookkeeping simple
    };

    auto compute_pair = [&](int buf) {
        uint32_t aBase = smemBase + buf * PAIR_B + lr * ROWB + lkb
                       + (wm * 32) * ROWB;
        uint32_t bBase = smemBase + buf * PAIR_B + MAT_A + lr * ROWB + lkb
                       + (wn * 32) * ROWB;
#pragma unroll
        for (int kk = 0; kk < 4; kk++) {
            uint32_t aF[2][4], bF[4][2];
#pragma unroll
            for (int im = 0; im < 2; im++)
                ldm4(aF[im], aBase + im * 16 * ROWB + kk * 32);
#pragma unroll
            for (int ig = 0; ig < 2; ig++) {
                uint32_t r[4];
                ldm4(r, bBase + ig * 16 * ROWB + kk * 32);
                bF[ig * 2][0] = r[0];     bF[ig * 2][1] = r[2];
                bF[ig * 2 + 1][0] = r[1]; bF[ig * 2 + 1][1] = r[3];
            }
#pragma unroll
            for (int im = 0; im < 2; im++)
#pragma unroll
                for (int iu = 0; iu < 4; iu++)
                    mma16816(acc[im][iu], aF[im], bF[iu]);
        }
    };

    // pair p lives in buffer p % 3
    issue_pair(0, 0);
    issue_pair(1, 1);
    int b0 = 0, b1 = 1, b2 = 2;
#pragma unroll 1
    for (int p = 0; p < NPAIR; p++) {
        CPWAIT1();                // this thread's group for pair p complete
        __syncthreads();          // => ALL threads' groups for pair p complete
        issue_pair(p + 2, b2);    // b2 last read at iter p-1, ordered by the barrier
        compute_pair(b0);
        int tmp = b0; b0 = b1; b1 = b2; b2 = tmp;
    }

    // ================= smem-staged epilogue =================
    __syncthreads();              // mainloop done: all smem free for staging
    const int ctaid = mt * 32 + nt;
    float* cblk = g_cblk + (size_t)ctaid * 4096;
    char* cst = smem;             // c stage: 128 rows x 36 f32 (pitch 144B)
    char* hst = smem + 20480;     // h stage: fp16 pitch 80B / f32 pitch 160B

    // coalesced c prefetch into smem
#pragma unroll
    for (int q0 = 0; q0 < 2; q0++) {
        int q = tid + q0 * 512;
        int row = q >> 3, ch = q & 7;
        CP16(smemBase + row * 144 + ch * 16, (const char*)(cblk + row * 32) + ch * 16);
    }
    CPCOMMIT();
    CPWAIT0();
    __syncthreads();

    const int g  = lane >> 2;
    const int t4 = lane & 3;
#pragma unroll
    for (int iu = 0; iu < 4; iu++) {
        int npl = wn * 32 + iu * 8 + 2 * t4;
        float b0f = g_bil[nt * 128 + npl], b1f = g_bil[nt * 128 + npl + 1];
#pragma unroll
        for (int im = 0; im < 2; im++) {
            float z0 = acc[im][iu][0] + b0f;
            float z1 = acc[im][iu][1] + b1f;
            float z2 = acc[im][iu][2] + b0f;
            float z3 = acc[im][iu][3] + b1f;
            float o0 = __shfl_xor_sync(0xFFFFFFFF, z0, 1);
            float o1 = __shfl_xor_sync(0xFFFFFFFF, z1, 1);
            float o2 = __shfl_xor_sync(0xFFFFFFFF, z2, 1);
            float o3 = __shfl_xor_sync(0xFFFFFFFF, z3, 1);
            if ((t4 & 1) == 0) {
                int j32 = npl >> 2;     // wn*8 + iu*2 + (t4>>1), 0..31
                int ml  = wm * 32 + im * 16 + g;
#pragma unroll
                for (int rr = 0; rr < 2; rr++) {
                    int m = ml + rr * 8;
                    float zi = rr ? z2 : z0, zf = rr ? z3 : z1;
                    float zg = rr ? o2 : o0, zo = rr ? o3 : o1;
                    float* cp = (float*)(cst + m * 144 + j32 * 4);
                    float cn = fsig(zf) * (*cp) + fsig(zi) * fmaxf(zg, 0.0f);
                    *cp = cn;
                    float h = fsig(zo) * fmaxf(cn, 0.0f);
                    if (t == Tsz - 1)
                        *(float*)(hst + m * 160 + j32 * 4) = h;
                    else
                        *(__half*)(hst + m * 80 + j32 * 2) = __float2half(h);
                }
            }
        }
    }
    __syncthreads();

    // coalesced writebacks
    if (t < Tsz - 1) {
        int row = tid >> 2, ch = tid & 3;
        uint4 v = *(uint4*)(hst + row * 80 + ch * 16);
        *(uint4*)((char*)(g_hB[dst] + (size_t)(mt * 128 + row) * 1024 + nt * 32) + ch * 16) = v;
    } else {
#pragma unroll
        for (int q0 = 0; q0 < 2; q0++) {
            int q = tid + q0 * 512;
            int row = q >> 3, ch = q & 7;
            uint4 v = *(uint4*)(hst + row * 160 + ch * 16);
            *(uint4*)((char*)(g_hflat + (size_t)(mt * 128 + row) * 1024 + nt * 32) + ch * 16) = v;
        }
    }
#pragma unroll
    for (int q0 = 0; q0 < 2; q0++) {
        int q = tid + q0 * 512;
        int row = q >> 3, ch = q & 7;
        uint4 v = *(uint4*)(cst + row * 144 + ch * 16);
        *(uint4*)((char*)(cblk + row * 32) + ch * 16) = v;
    }
}

// ---------------- dense head ----------------
__global__ void dense_kernel(const float* __restrict__ Wd,
                             const float* __restrict__ bd,
                             float* __restrict__ out) {
    int m = blockIdx.x, o = threadIdx.x;
    if (o >= OUTsz) return;
    const float* hr = g_hflat + (size_t)m * Hsz;
    float acc = bd[o];
#pragma unroll 4
    for (int k = 0; k < Hsz; k++)
        acc = fmaf(hr[k], Wd[(size_t)k * OUTsz + o], acc);
    out[(size_t)m * OUTsz + o] = acc;
}

// ---------------------------------------------------------------------------
extern "C" void kernel_launch(void* const* d_in, const int* in_sizes, int n_in,
                              void* d_out, int out_size) {
    const float* x  = (const float*)d_in[0];
    const float* W  = (const float*)d_in[1];
    const float* U  = (const float*)d_in[2];
    const float* b  = (const float*)d_in[3];
    const float* Wd = (const float*)d_in[4];
    const float* bd = (const float*)d_in[5];
    float* out = (float*)d_out;

    static int attr_set = 0;
    if (!attr_set) {
        cudaFuncSetAttribute(step_kernel, cudaFuncAttributeMaxDynamicSharedMemorySize,
                             SMEM_TOTAL);
        attr_set = 1;
    }

    k_init<<<(int)((TOTI + 255) / 256), 256>>>(x, W, U, b);

    dim3 grid(32, 16);
    for (int t = 0; t < Tsz; t++)
        step_kernel<<<grid, 512, SMEM_TOTAL>>>(t);

    dense_kernel<<<Bsz, 32>>>(Wd, bd, out);
}

// round 16
// speedup vs baseline: 1.9885x; 1.1013x over previous
#include <cuda_runtime.h>
#include <cuda_fp16.h>
#include <cstdint>
#include <math.h>

#define Bsz 2048
#define Tsz 60
#define Fsz 89
#define Hsz 1024
#define OUTsz 30

#define NPAIR 18           // 16 pairs of 64K (h@U) + 2 pairs (x@W, padded 96->128)
#define ROWB 144           // smem row pitch: 64 fp16 (128B) + 16B pad (conflict-free)
#define MAT_A 18432        // 128 rows * 144
#define PAIR_B 36864       // A + B
#define NBUF 3
#define SMEM_TOTAL (NBUF * PAIR_B)   // 110592 -> 2 CTAs/SM
#define NJOBS (Tsz * 512)

// ---------------- device globals (no runtime allocation) ----------------
__device__ __align__(16) __half g_UB[(size_t)4096 * 1024];      // [np][k], np = 4*j+gate
__device__ __align__(16) __half g_WB[(size_t)4096 * 128];       // [np][k], k padded to 128
__device__ __align__(16) __half g_xB[(size_t)2048 * 60 * 128];  // [m][t][128], padded
__device__ __align__(16) __half g_hB3[3][(size_t)2048 * 1024];  // h ring: step t reads t%3, writes (t+1)%3
__device__ __align__(16) float g_cblk[(size_t)512 * 4096];      // c, CTA-blocked [tile][128][32]
__device__ float g_hflat[(size_t)2048 * 1024];
__device__ float g_bil[4096];
__device__ int   g_flag[Tsz * 16];                              // completed (t, mt) producer count

// ---------------- PTX helpers (baseline ISA only) ----------------
__device__ __forceinline__ uint32_t smem_u32(const void* p) {
    uint32_t a;
    asm("{ .reg .u64 t; cvta.to.shared.u64 t, %1; cvt.u32.u64 %0, t; }" : "=r"(a) : "l"(p));
    return a;
}
#define CP16(dst, src) \
    asm volatile("cp.async.cg.shared.global [%0], [%1], 16;" :: "r"(dst), "l"(src))
#define CP16O(dst, src, off) \
    asm volatile("cp.async.cg.shared.global [%0], [%1+%2], 16;" :: "r"(dst), "l"(src), "n"(off))
#define CPCOMMIT() asm volatile("cp.async.commit_group;" ::: "memory")
#define CPWAIT1()  asm volatile("cp.async.wait_group 1;" ::: "memory")
#define CPWAIT0()  asm volatile("cp.async.wait_group 0;" ::: "memory")

__device__ __forceinline__ void ldm4(uint32_t* r, uint32_t addr) {
    asm volatile("ldmatrix.sync.aligned.m8n8.x4.shared.b16 {%0,%1,%2,%3}, [%4];"
        : "=r"(r[0]), "=r"(r[1]), "=r"(r[2]), "=r"(r[3]) : "r"(addr));
}
__device__ __forceinline__ void mma16816(float* d, const uint32_t* a, const uint32_t* b) {
    asm volatile(
        "mma.sync.aligned.m16n8k16.row.col.f32.f16.f16.f32 "
        "{%0,%1,%2,%3}, {%4,%5,%6,%7}, {%8,%9}, {%0,%1,%2,%3};"
        : "+f"(d[0]), "+f"(d[1]), "+f"(d[2]), "+f"(d[3])
        : "r"(a[0]), "r"(a[1]), "r"(a[2]), "r"(a[3]), "r"(b[0]), "r"(b[1]));
}

// fast sigmoid: rcp.approx(1 + 2^(-x*log2(e)))
__device__ __forceinline__ float fsig(float x) {
    float e, r;
    asm("ex2.approx.f32 %0, %1;" : "=f"(e) : "f"(-1.4426950408889634f * x));
    asm("rcp.approx.f32 %0, %1;" : "=f"(r) : "f"(1.0f + e));
    return r;
}

// ---------------- single merged init/repack kernel ----------------
#define SEG0 ((size_t)2048 * 1024)        // zero cblk, h ring slot 0
#define SEG1 ((size_t)1024 * 4096)        // repack U
#define SEG2 ((size_t)128 * 4096)         // repack W (padded K)
#define SEG3 ((size_t)2048 * 60 * 128)    // repack x (padded F)
#define SEG4 ((size_t)4096)               // repack bias
#define SEG5 ((size_t)(Tsz * 16))         // zero flags
#define TOTI (SEG0 + SEG1 + SEG2 + SEG3 + SEG4 + SEG5)

__global__ void k_init(const float* __restrict__ x, const float* __restrict__ W,
                       const float* __restrict__ U, const float* __restrict__ b) {
    size_t i = (size_t)blockIdx.x * 256 + threadIdx.x;
    if (i < SEG0) {
        g_cblk[i] = 0.0f;
        g_hB3[0][i] = __float2half(0.0f);
        return;
    }
    i -= SEG0;
    if (i < SEG1) {
        int k = (int)(i >> 12), c = (int)(i & 4095);
        int np = 4 * (c & 1023) + (c >> 10);
        g_UB[(size_t)np * 1024 + k] = __float2half(U[i]);
        return;
    }
    i -= SEG1;
    if (i < SEG2) {
        int k = (int)(i >> 12), c = (int)(i & 4095);
        float v = (k < Fsz) ? W[(size_t)k * 4096 + c] : 0.0f;
        int np = 4 * (c & 1023) + (c >> 10);
        g_WB[(size_t)np * 128 + k] = __float2half(v);
        return;
    }
    i -= SEG2;
    if (i < SEG3) {
        int k = (int)(i & 127);
        size_t mt_ = i >> 7;   // m*60 + t
        float v = (k < Fsz) ? x[mt_ * Fsz + k] : 0.0f;
        g_xB[i] = __float2half(v);
        return;
    }
    i -= SEG3;
    if (i < SEG4) {
        int c = (int)i;
        g_bil[4 * (c & 1023) + (c >> 10)] = b[c];
        return;
    }
    i -= SEG4;
    if (i < SEG5) g_flag[i] = 0;
}

// ---------------- persistent fused LSTM kernel ----------------
// Jobs (t, mt, nt) over a static round-robin queue; per-(t,mt) release flags
// gate cross-step h dependencies. Deps point strictly backward in job index,
// so with all CTAs co-resident the minimal unfinished job can always run.
__global__ __launch_bounds__(512, 2) void persist_kernel() {
    extern __shared__ __align__(128) char smem[];
    const int tid  = threadIdx.x;
    const int wid  = tid >> 5, lane = tid & 31;
    const int wm   = wid >> 2, wn = wid & 3;
    const int lr   = lane & 15;
    const int lkb  = ((lane >> 4) & 1) * 16;
    const uint32_t smemBase = smem_u32(smem);
    const int rA = tid >> 3;          // 0..63
    const int kc = tid & 7;           // 16B chunk
    const uint32_t dA0 = rA * ROWB + kc * 16;
    const uint32_t dB0 = MAT_A + dA0;
    const int g  = lane >> 2;
    const int t4 = lane & 3;
    const int G  = gridDim.x;

#pragma unroll 1
    for (int J = blockIdx.x; J < NJOBS; J += G) {
        const int t    = J >> 9;
        const int tile = J & 511;
        const int mt   = tile >> 5, nt = tile & 31;
        const int src  = t % 3, dst = (t + 1) % 3;

        // ---- wait for step t-1 producers of rows [128*mt, +128) ----
        if (t > 0) {
            if (tid == 0) {
                const int* fp = &g_flag[(t - 1) * 16 + mt];
                int v;
                while (true) {
                    asm volatile("ld.acquire.gpu.global.s32 %0, [%1];" : "=r"(v) : "l"(fp));
                    if (v >= 32) break;
                    __nanosleep(64);
                }
            }
            __syncthreads();
        }

        float acc[2][4][4];
#pragma unroll
        for (int a = 0; a < 2; a++)
#pragma unroll
            for (int b = 0; b < 4; b++)
#pragma unroll
                for (int c = 0; c < 4; c++) acc[a][b][c] = 0.0f;

        const char* pA = (const char*)(g_hB3[src] + (size_t)(mt * 128 + rA) * 1024 + kc * 8);
        const char* pB = (const char*)(g_UB      + (size_t)(nt * 128 + rA) * 1024 + kc * 8);

        auto issue_pair = [&](int p, int buf) {
            if (p < NPAIR) {
                uint32_t sb = smemBase + buf * PAIR_B;
                if (p < 16) {
                    CP16O(sb + dA0,        pA, 0);
                    CP16O(sb + dA0 + 9216, pA, 131072);   // +64 rows
                    CP16O(sb + dB0,        pB, 0);
                    CP16O(sb + dB0 + 9216, pB, 131072);
                    pA += 128;
                    pB += 128;
                } else {
                    int i = p - 16;
#pragma unroll
                    for (int it = 0; it < 2; it++) {
                        int row = rA + 64 * it;
                        CP16(sb + dA0 + it * 9216,
                             g_xB + (size_t)(mt * 128 + row) * (Tsz * 128)
                                  + (size_t)t * 128 + 64 * i + kc * 8);
                        CP16(sb + dB0 + it * 9216,
                             g_WB + (size_t)(nt * 128 + row) * 128 + 64 * i + kc * 8);
                    }
                }
            }
            CPCOMMIT();
        };

        auto compute_pair = [&](int buf) {
            uint32_t aBase = smemBase + buf * PAIR_B + lr * ROWB + lkb
                           + (wm * 32) * ROWB;
            uint32_t bBase = smemBase + buf * PAIR_B + MAT_A + lr * ROWB + lkb
                           + (wn * 32) * ROWB;
#pragma unroll
            for (int kk = 0; kk < 4; kk++) {
                uint32_t aF[2][4], bF[4][2];
#pragma unroll
                for (int im = 0; im < 2; im++)
                    ldm4(aF[im], aBase + im * 16 * ROWB + kk * 32);
#pragma unroll
                for (int ig = 0; ig < 2; ig++) {
                    uint32_t r[4];
                    ldm4(r, bBase + ig * 16 * ROWB + kk * 32);
                    bF[ig * 2][0] = r[0];     bF[ig * 2][1] = r[2];
                    bF[ig * 2 + 1][0] = r[1]; bF[ig * 2 + 1][1] = r[3];
                }
#pragma unroll
                for (int im = 0; im < 2; im++)
#pragma unroll
                    for (int iu = 0; iu < 4; iu++)
                        mma16816(acc[im][iu], aF[im], bF[iu]);
            }
        };

        issue_pair(0, 0);
        issue_pair(1, 1);
        int b0 = 0, b1 = 1, b2 = 2;
#pragma unroll 1
        for (int p = 0; p < NPAIR; p++) {
            CPWAIT1();                // this thread's group for pair p complete
            __syncthreads();          // => ALL threads' groups for pair p complete
            issue_pair(p + 2, b2);    // b2 last read at iter p-1, ordered by the barrier
            compute_pair(b0);
            int tmp = b0; b0 = b1; b1 = b2; b2 = tmp;
        }

        // ================= smem-staged epilogue =================
        __syncthreads();
        float* cblk = g_cblk + (size_t)tile * 4096;
        char* cst = smem;             // c stage: 128 rows x pitch 144B
        char* hst = smem + 20480;     // h stage: fp16 pitch 80B / f32 pitch 160B

#pragma unroll
        for (int q0 = 0; q0 < 2; q0++) {
            int q = tid + q0 * 512;
            int row = q >> 3, ch = q & 7;
            CP16(smemBase + row * 144 + ch * 16, (const char*)(cblk + row * 32) + ch * 16);
        }
        CPCOMMIT();
        CPWAIT0();
        __syncthreads();

#pragma unroll
        for (int iu = 0; iu < 4; iu++) {
            int npl = wn * 32 + iu * 8 + 2 * t4;
            float b0f = g_bil[nt * 128 + npl], b1f = g_bil[nt * 128 + npl + 1];
#pragma unroll
            for (int im = 0; im < 2; im++) {
                float z0 = acc[im][iu][0] + b0f;
                float z1 = acc[im][iu][1] + b1f;
                float z2 = acc[im][iu][2] + b0f;
                float z3 = acc[im][iu][3] + b1f;
                float o0 = __shfl_xor_sync(0xFFFFFFFF, z0, 1);
                float o1 = __shfl_xor_sync(0xFFFFFFFF, z1, 1);
                float o2 = __shfl_xor_sync(0xFFFFFFFF, z2, 1);
                float o3 = __shfl_xor_sync(0xFFFFFFFF, z3, 1);
                if ((t4 & 1) == 0) {
                    int j32 = npl >> 2;
                    int ml  = wm * 32 + im * 16 + g;
#pragma unroll
                    for (int rr = 0; rr < 2; rr++) {
                        int m = ml + rr * 8;
                        float zi = rr ? z2 : z0, zf = rr ? z3 : z1;
                        float zg = rr ? o2 : o0, zo = rr ? o3 : o1;
                        float* cp = (float*)(cst + m * 144 + j32 * 4);
                        float cn = fsig(zf) * (*cp) + fsig(zi) * fmaxf(zg, 0.0f);
                        *cp = cn;
                        float h = fsig(zo) * fmaxf(cn, 0.0f);
                        if (t == Tsz - 1)
                            *(float*)(hst + m * 160 + j32 * 4) = h;
                        else
                            *(__half*)(hst + m * 80 + j32 * 2) = __float2half(h);
                    }
                }
            }
        }
        __syncthreads();

        // coalesced writebacks
        if (t < Tsz - 1) {
            int row = tid >> 2, ch = tid & 3;
            uint4 v = *(uint4*)(hst + row * 80 + ch * 16);
            *(uint4*)((char*)(g_hB3[dst] + (size_t)(mt * 128 + row) * 1024 + nt * 32) + ch * 16) = v;
        } else {
#pragma unroll
            for (int q0 = 0; q0 < 2; q0++) {
                int q = tid + q0 * 512;
                int row = q >> 3, ch = q & 7;
                uint4 v = *(uint4*)(hst + row * 160 + ch * 16);
                *(uint4*)((char*)(g_hflat + (size_t)(mt * 128 + row) * 1024 + nt * 32) + ch * 16) = v;
            }
        }
#pragma unroll
        for (int q0 = 0; q0 < 2; q0++) {
            int q = tid + q0 * 512;
            int row = q >> 3, ch = q & 7;
            uint4 v = *(uint4*)(cst + row * 144 + ch * 16);
            *(uint4*)((char*)(cblk + row * 32) + ch * 16) = v;
        }

        // publish: all CTA writes fenced, then release-increment the (t, mt) flag.
        __syncthreads();              // also orders epilogue smem reads before next job's cp.async
        if (tid == 0) {
            __threadfence();
            atomicAdd(&g_flag[t * 16 + mt], 1);
        }
    }
}

// ---------------- dense head ----------------
__global__ void dense_kernel(const float* __restrict__ Wd,
                             const float* __restrict__ bd,
                             float* __restrict__ out) {
    int m = blockIdx.x, o = threadIdx.x;
    if (o >= OUTsz) return;
    const float* hr = g_hflat + (size_t)m * Hsz;
    float acc = bd[o];
#pragma unroll 4
    for (int k = 0; k < Hsz; k++)
        acc = fmaf(hr[k], Wd[(size_t)k * OUTsz + o], acc);
    out[(size_t)m * OUTsz + o] = acc;
}

// ---------------------------------------------------------------------------
extern "C" void kernel_launch(void* const* d_in, const int* in_sizes, int n_in,
                              void* d_out, int out_size) {
    const float* x  = (const float*)d_in[0];
    const float* W  = (const float*)d_in[1];
    const float* U  = (const float*)d_in[2];
    const float* b  = (const float*)d_in[3];
    const float* Wd = (const float*)d_in[4];
    const float* bd = (const float*)d_in[5];
    float* out = (float*)d_out;

    static int grid = 0;
    if (!grid) {
        cudaFuncSetAttribute(persist_kernel, cudaFuncAttributeMaxDynamicSharedMemorySize,
                             SMEM_TOTAL);
        int dev = 0, nsm = 0, nb = 0;
        cudaGetDevice(&dev);
        cudaDeviceGetAttribute(&nsm, cudaDevAttrMultiProcessorCount, dev);
        cudaOccupancyMaxActiveBlocksPerMultiprocessor(&nb, persist_kernel, 512, SMEM_TOTAL);
        if (nsm < 1) nsm = 148;          // defensive fallback
        if (nb < 1) nb = 1;              // 1 CTA/SM is always co-resident
        grid = nsm * nb;
        if (grid > NJOBS) grid = NJOBS;
    }

    k_init<<<(int)((TOTI + 255) / 256), 256>>>(x, W, U, b);
    persist_kernel<<<grid, 512, SMEM_TOTAL>>>();
    dense_kernel<<<Bsz, 32>>>(Wd, bd, out);
}